// round 1
// baseline (speedup 1.0000x reference)
#include <cuda_runtime.h>
#include <cuda_bf16.h>
#include <math.h>

#define U 2048
#define D 2048
#define N_HEADS 16
#define D_HEAD 128
#define D_FF 8192
#define EPS 1e-6f

// ---------------- scratch (device globals: allocation-free) ----------------
__device__ float g_h[(size_t)U * D];        // h (pre-attn norm) / h2 (pre-ffn norm)
__device__ float g_q[(size_t)U * D];
__device__ float g_k[(size_t)U * D];
__device__ float g_v[(size_t)U * D];
__device__ float g_scores[(size_t)N_HEADS * U * U];   // 256 MB
__device__ float g_attn_out[(size_t)U * D];
__device__ float g_x2[(size_t)U * D];       // x after attention residual
__device__ float g_ff[(size_t)U * D_FF];    // 64 MB

// ---------------- RMSNorm ----------------
__global__ void rmsnorm_kernel(const float* __restrict__ x,
                               const float* __restrict__ w,
                               float* __restrict__ out) {
    const int row = blockIdx.x;
    const float* xr = x + (size_t)row * D;
    float* orow = out + (size_t)row * D;
    const int tid = threadIdx.x;
    __shared__ float red[8];

    float ss = 0.f;
    for (int i = tid; i < D; i += 256) { float v = xr[i]; ss += v * v; }
    #pragma unroll
    for (int o = 16; o; o >>= 1) ss += __shfl_xor_sync(0xffffffffu, ss, o);
    if ((tid & 31) == 0) red[tid >> 5] = ss;
    __syncthreads();
    float tot = 0.f;
    #pragma unroll
    for (int i = 0; i < 8; i++) tot += red[i];
    const float r = rsqrtf(tot / (float)D + EPS);
    for (int i = tid; i < D; i += 256) orow[i] = xr[i] * r * w[i];
}

// ---------------- softmax over rows of length U ----------------
__global__ void softmax_kernel(float* __restrict__ s) {
    float* p = s + (size_t)blockIdx.x * U;
    const int tid = threadIdx.x;
    __shared__ float red[8];

    float m = -1e30f;
    for (int i = tid; i < U; i += 256) m = fmaxf(m, p[i]);
    #pragma unroll
    for (int o = 16; o; o >>= 1) m = fmaxf(m, __shfl_xor_sync(0xffffffffu, m, o));
    if ((tid & 31) == 0) red[tid >> 5] = m;
    __syncthreads();
    #pragma unroll
    for (int i = 0; i < 8; i++) m = fmaxf(m, red[i]);
    __syncthreads();

    float sum = 0.f;
    for (int i = tid; i < U; i += 256) {
        float e = __expf(p[i] - m);
        p[i] = e;
        sum += e;
    }
    #pragma unroll
    for (int o = 16; o; o >>= 1) sum += __shfl_xor_sync(0xffffffffu, sum, o);
    if ((tid & 31) == 0) red[tid >> 5] = sum;
    __syncthreads();
    float tot = 0.f;
    #pragma unroll
    for (int i = 0; i < 8; i++) tot += red[i];
    const float inv = 1.0f / tot;
    for (int i = tid; i < U; i += 256) p[i] *= inv;
}

// ---------------- NT GEMM: C[m,n] = sum_k A[m,k] * B[n,k]  (+epilogue) -----
// 128x128 tile, BK=16, 256 threads, 8x8 per thread. Batched via blockIdx.z.
#define BM 128
#define BN 128
#define BK 16

__global__ __launch_bounds__(256, 2)
void gemm_nt_kernel(const float* __restrict__ A, int lda, size_t sA,
                    const float* __restrict__ B, int ldb, size_t sB,
                    float* __restrict__ C, int ldc, size_t sC,
                    int K,
                    const float* __restrict__ bias,      // [N] or null
                    const float* __restrict__ bias2d, int ld2,  // [M,N] or null
                    const float* __restrict__ residual, int ldr, // [M,N] or null
                    float scale, int do_gelu) {
    __shared__ float As[BK][BM];
    __shared__ float Bs[BK][BN];

    const int z = blockIdx.z;
    A += (size_t)z * sA; B += (size_t)z * sB; C += (size_t)z * sC;

    const int bm = blockIdx.y * BM;
    const int bn = blockIdx.x * BN;
    const int tid = threadIdx.x;
    const int tx = tid & 15, ty = tid >> 4;

    float acc[8][8];
    #pragma unroll
    for (int i = 0; i < 8; i++)
        #pragma unroll
        for (int j = 0; j < 8; j++) acc[i][j] = 0.f;

    for (int k0 = 0; k0 < K; k0 += BK) {
        #pragma unroll
        for (int it = 0; it < 2; it++) {
            int e = tid + it * 256;
            int row = e >> 2;
            int c4 = (e & 3) << 2;
            float4 va = *(const float4*)(A + (size_t)(bm + row) * lda + k0 + c4);
            As[c4 + 0][row] = va.x; As[c4 + 1][row] = va.y;
            As[c4 + 2][row] = va.z; As[c4 + 3][row] = va.w;
            float4 vb = *(const float4*)(B + (size_t)(bn + row) * ldb + k0 + c4);
            Bs[c4 + 0][row] = vb.x; Bs[c4 + 1][row] = vb.y;
            Bs[c4 + 2][row] = vb.z; Bs[c4 + 3][row] = vb.w;
        }
        __syncthreads();
        #pragma unroll
        for (int kk = 0; kk < BK; kk++) {
            float a[8], b[8];
            #pragma unroll
            for (int i = 0; i < 8; i++) a[i] = As[kk][ty * 8 + i];
            #pragma unroll
            for (int j = 0; j < 8; j++) b[j] = Bs[kk][tx * 8 + j];
            #pragma unroll
            for (int i = 0; i < 8; i++)
                #pragma unroll
                for (int j = 0; j < 8; j++) acc[i][j] += a[i] * b[j];
        }
        __syncthreads();
    }

    #pragma unroll
    for (int i = 0; i < 8; i++) {
        const int row = bm + ty * 8 + i;
        #pragma unroll
        for (int j = 0; j < 8; j++) {
            const int col = bn + tx * 8 + j;
            float v = acc[i][j] * scale;
            if (bias)   v += bias[col];
            if (bias2d) v += bias2d[(size_t)row * ld2 + col];
            if (do_gelu) v = 0.5f * v * (1.0f + erff(v * 0.70710678118654752f));
            if (residual) v += residual[(size_t)row * ldr + col];
            C[(size_t)row * ldc + col] = v;
        }
    }
}

// ---------------- NN GEMM: C[m,n] = sum_k A[m,k] * B[k,n]  (PV) ------------
__global__ __launch_bounds__(256, 2)
void gemm_nn_kernel(const float* __restrict__ A, int lda, size_t sA,
                    const float* __restrict__ B, int ldb, size_t sB,
                    float* __restrict__ C, int ldc, size_t sC,
                    int K) {
    __shared__ float As[BK][BM];
    __shared__ float Bs[BK][BN];

    const int z = blockIdx.z;
    A += (size_t)z * sA; B += (size_t)z * sB; C += (size_t)z * sC;

    const int bm = blockIdx.y * BM;
    const int bn = blockIdx.x * BN;
    const int tid = threadIdx.x;
    const int tx = tid & 15, ty = tid >> 4;

    float acc[8][8];
    #pragma unroll
    for (int i = 0; i < 8; i++)
        #pragma unroll
        for (int j = 0; j < 8; j++) acc[i][j] = 0.f;

    for (int k0 = 0; k0 < K; k0 += BK) {
        #pragma unroll
        for (int it = 0; it < 2; it++) {
            int e = tid + it * 256;
            // A tile: BM rows x BK cols
            int rowA = e >> 2;
            int c4A = (e & 3) << 2;
            float4 va = *(const float4*)(A + (size_t)(bm + rowA) * lda + k0 + c4A);
            As[c4A + 0][rowA] = va.x; As[c4A + 1][rowA] = va.y;
            As[c4A + 2][rowA] = va.z; As[c4A + 3][rowA] = va.w;
            // B tile: BK rows x BN cols (row-major direct)
            int kkB = e >> 5;            // 32 float4 per row of 128
            int c4B = (e & 31) << 2;
            float4 vb = *(const float4*)(B + (size_t)(k0 + kkB) * ldb + bn + c4B);
            Bs[kkB][c4B + 0] = vb.x; Bs[kkB][c4B + 1] = vb.y;
            Bs[kkB][c4B + 2] = vb.z; Bs[kkB][c4B + 3] = vb.w;
        }
        __syncthreads();
        #pragma unroll
        for (int kk = 0; kk < BK; kk++) {
            float a[8], b[8];
            #pragma unroll
            for (int i = 0; i < 8; i++) a[i] = As[kk][ty * 8 + i];
            #pragma unroll
            for (int j = 0; j < 8; j++) b[j] = Bs[kk][tx * 8 + j];
            #pragma unroll
            for (int i = 0; i < 8; i++)
                #pragma unroll
                for (int j = 0; j < 8; j++) acc[i][j] += a[i] * b[j];
        }
        __syncthreads();
    }

    #pragma unroll
    for (int i = 0; i < 8; i++) {
        const int row = bm + ty * 8 + i;
        #pragma unroll
        for (int j = 0; j < 8; j++) {
            const int col = bn + tx * 8 + j;
            C[(size_t)row * ldc + col] = acc[i][j];
        }
    }
}

// ---------------- launch ----------------
extern "C" void kernel_launch(void* const* d_in, const int* in_sizes, int n_in,
                              void* d_out, int out_size) {
    const float* x    = (const float*)d_in[0];
    const float* adj  = (const float*)d_in[1];
    const float* n1w  = (const float*)d_in[2];
    const float* n2w  = (const float*)d_in[3];
    const float* wq   = (const float*)d_in[4];
    const float* wk   = (const float*)d_in[5];
    const float* wv   = (const float*)d_in[6];
    const float* wo   = (const float*)d_in[7];
    const float* wup  = (const float*)d_in[8];
    const float* bup  = (const float*)d_in[9];
    const float* wdn  = (const float*)d_in[10];
    const float* bdn  = (const float*)d_in[11];
    float* out = (float*)d_out;

    float *h, *q, *k, *v, *sc, *ao, *x2, *ff;
    cudaGetSymbolAddress((void**)&h,  g_h);
    cudaGetSymbolAddress((void**)&q,  g_q);
    cudaGetSymbolAddress((void**)&k,  g_k);
    cudaGetSymbolAddress((void**)&v,  g_v);
    cudaGetSymbolAddress((void**)&sc, g_scores);
    cudaGetSymbolAddress((void**)&ao, g_attn_out);
    cudaGetSymbolAddress((void**)&x2, g_x2);
    cudaGetSymbolAddress((void**)&ff, g_ff);

    const float attn_scale = 0.08838834764831845f; // 1/sqrt(128)

    // 1) h = rmsnorm(x, norm1_w)
    rmsnorm_kernel<<<U, 256>>>(x, n1w, h);

    // 2-4) q/k/v = h @ W^T
    dim3 gQKV(D / BN, U / BM, 1);
    gemm_nt_kernel<<<gQKV, 256>>>(h, D, 0, wq, D, 0, q, D, 0, D,
                                  nullptr, nullptr, 0, nullptr, 0, 1.0f, 0);
    gemm_nt_kernel<<<gQKV, 256>>>(h, D, 0, wk, D, 0, k, D, 0, D,
                                  nullptr, nullptr, 0, nullptr, 0, 1.0f, 0);
    gemm_nt_kernel<<<gQKV, 256>>>(h, D, 0, wv, D, 0, v, D, 0, D,
                                  nullptr, nullptr, 0, nullptr, 0, 1.0f, 0);

    // 5) scores[h] = q_h k_h^T * scale + adj_bias  (batched over heads)
    dim3 gS(U / BN, U / BM, N_HEADS);
    gemm_nt_kernel<<<gS, 256>>>(q, D, (size_t)D_HEAD,
                                k, D, (size_t)D_HEAD,
                                sc, U, (size_t)U * U,
                                D_HEAD,
                                nullptr, adj, U, nullptr, 0, attn_scale, 0);

    // 6) softmax rows
    softmax_kernel<<<N_HEADS * U, 256>>>(sc);

    // 7) attn_out[:, h*128:(h+1)*128] = attn_h @ v_h   (batched)
    dim3 gPV(D_HEAD / BN, U / BM, N_HEADS);
    gemm_nn_kernel<<<gPV, 256>>>(sc, U, (size_t)U * U,
                                 v, D, (size_t)D_HEAD,
                                 ao, D, (size_t)D_HEAD,
                                 U);

    // 8) x2 = x + attn_out @ wo^T
    gemm_nt_kernel<<<gQKV, 256>>>(ao, D, 0, wo, D, 0, x2, D, 0, D,
                                  nullptr, nullptr, 0, x, D, 1.0f, 0);

    // 9) h2 = rmsnorm(x2, norm2_w)   (reuse h buffer)
    rmsnorm_kernel<<<U, 256>>>(x2, n2w, h);

    // 10) ff = gelu(h2 @ w_up^T + b_up)
    dim3 gUP(D_FF / BN, U / BM, 1);
    gemm_nt_kernel<<<gUP, 256>>>(h, D, 0, wup, D, 0, ff, D_FF, 0, D,
                                 bup, nullptr, 0, nullptr, 0, 1.0f, 1);

    // 11) out = x2 + ff @ w_down^T + b_down
    dim3 gDN(D / BN, U / BM, 1);
    gemm_nt_kernel<<<gDN, 256>>>(ff, D_FF, 0, wdn, D_FF, 0, out, D, 0, D_FF,
                                 bdn, nullptr, 0, x2, D, 1.0f, 0);
}

// round 3
// speedup vs baseline: 1.7545x; 1.7545x over previous
#include <cuda_runtime.h>
#include <cuda_bf16.h>
#include <math.h>
#include <stdint.h>

#define U 2048
#define D 2048
#define N_HEADS 16
#define D_HEAD 128
#define D_FF 8192
#define EPS 1e-6f

#define K3D (3*D)       // 6144
#define K3H (3*D_HEAD)  // 384
#define K3F (3*D_FF)    // 24576
#define K3U (3*U)       // 6144

// ---------------- scratch (device globals: allocation-free) ----------------
__device__ float g_scores[(size_t)N_HEADS * U * U];       // 256 MB fp32
__device__ float g_x2[(size_t)U * D];
__device__ float g_v[(size_t)U * D];
__device__ __nv_bfloat16 g_h3 [(size_t)U * K3D];          // h triple / ao3 / h2 triple
__device__ __nv_bfloat16 g_q3 [(size_t)U * K3D];
__device__ __nv_bfloat16 g_k3 [(size_t)U * K3D];
__device__ __nv_bfloat16 g_vT3[(size_t)D * K3U];
__device__ __nv_bfloat16 g_attn3[(size_t)N_HEADS * U * K3U];  // 384 MiB
__device__ __nv_bfloat16 g_ff3[(size_t)U * K3F];
__device__ __nv_bfloat16 g_wq3[(size_t)D * K3D];
__device__ __nv_bfloat16 g_wk3[(size_t)D * K3D];
__device__ __nv_bfloat16 g_wv3[(size_t)D * K3D];
__device__ __nv_bfloat16 g_wo3[(size_t)D * K3D];
__device__ __nv_bfloat16 g_wup3[(size_t)D_FF * K3D];
__device__ __nv_bfloat16 g_wdn3[(size_t)D * K3F];

// ---------------- helpers ----------------
__device__ __forceinline__ void split2(float x, __nv_bfloat16& hi, __nv_bfloat16& lo) {
    hi = __float2bfloat16(x);
    lo = __float2bfloat16(x - __bfloat162float(hi));
}
__device__ __forceinline__ __nv_bfloat162 mk2(__nv_bfloat16 a, __nv_bfloat16 b) {
    __nv_bfloat162 r; r.x = a; r.y = b; return r;
}
// A-style pair (h0,l0,h0 | h1,l1,h1) -> 3 bf162 words
__device__ __forceinline__ void trip_a_pair(__nv_bfloat162* p, float x0, float x1) {
    __nv_bfloat16 h0, l0, h1, l1; split2(x0, h0, l0); split2(x1, h1, l1);
    p[0] = mk2(h0, l0); p[1] = mk2(h0, h1); p[2] = mk2(l1, h1);
}
// B-style pair (h0,h0,l0 | h1,h1,l1)
__device__ __forceinline__ void trip_b_pair(__nv_bfloat162* p, float x0, float x1) {
    __nv_bfloat16 h0, l0, h1, l1; split2(x0, h0, l0); split2(x1, h1, l1);
    p[0] = mk2(h0, h0); p[1] = mk2(l0, h1); p[2] = mk2(h1, l1);
}

__device__ __forceinline__ void cp16(void* smem, const void* gmem) {
    uint32_t s = (uint32_t)__cvta_generic_to_shared(smem);
    asm volatile("cp.async.ca.shared.global [%0], [%1], 16;\n" :: "r"(s), "l"(gmem));
}
__device__ __forceinline__ void cpcommit() { asm volatile("cp.async.commit_group;\n"); }
__device__ __forceinline__ void cpwait0() { asm volatile("cp.async.wait_group 0;\n"); }
__device__ __forceinline__ void cpwait1() { asm volatile("cp.async.wait_group 1;\n"); }

__device__ __forceinline__ void mma16816(float* c, const uint32_t* a, const uint32_t* b) {
    asm volatile(
        "mma.sync.aligned.m16n8k16.row.col.f32.bf16.bf16.f32 "
        "{%0,%1,%2,%3}, {%4,%5,%6,%7}, {%8,%9}, {%0,%1,%2,%3};\n"
        : "+f"(c[0]), "+f"(c[1]), "+f"(c[2]), "+f"(c[3])
        : "r"(a[0]), "r"(a[1]), "r"(a[2]), "r"(a[3]), "r"(b[0]), "r"(b[1]));
}

// ---------------- triple conversion (fp32 [R,C] -> bf16 [R,3C]) ------------
__global__ void conv_triple_kernel(const float* __restrict__ in,
                                   __nv_bfloat16* __restrict__ out,
                                   size_t n8, int styleB) {
    size_t g = (size_t)blockIdx.x * 256 + threadIdx.x;
    if (g >= n8) return;
    const float4* p = (const float4*)(in + g * 8);
    float4 a = p[0], b = p[1];
    float xs[8] = {a.x, a.y, a.z, a.w, b.x, b.y, b.z, b.w};
    __nv_bfloat162* o = (__nv_bfloat162*)(out + g * 24);
    if (styleB) {
        #pragma unroll
        for (int m = 0; m < 4; m++) trip_b_pair(o + 3 * m, xs[2 * m], xs[2 * m + 1]);
    } else {
        #pragma unroll
        for (int m = 0; m < 4; m++) trip_a_pair(o + 3 * m, xs[2 * m], xs[2 * m + 1]);
    }
}

// ---------------- RMSNorm -> A-style triple ----------------
__global__ void rmsnorm_triple_kernel(const float* __restrict__ x,
                                      const float* __restrict__ w,
                                      __nv_bfloat16* __restrict__ out) {
    const int row = blockIdx.x;
    const int tid = threadIdx.x;
    __shared__ float red[8];
    const float4* xr = (const float4*)(x + (size_t)row * D + tid * 8);
    const float4* wr = (const float4*)(w + tid * 8);
    float4 xa = xr[0], xb = xr[1];
    float4 wa = wr[0], wb = wr[1];
    float xs[8] = {xa.x, xa.y, xa.z, xa.w, xb.x, xb.y, xb.z, xb.w};
    float ws[8] = {wa.x, wa.y, wa.z, wa.w, wb.x, wb.y, wb.z, wb.w};
    float ss = 0.f;
    #pragma unroll
    for (int i = 0; i < 8; i++) ss += xs[i] * xs[i];
    #pragma unroll
    for (int o = 16; o; o >>= 1) ss += __shfl_xor_sync(0xffffffffu, ss, o);
    if ((tid & 31) == 0) red[tid >> 5] = ss;
    __syncthreads();
    float tot = 0.f;
    #pragma unroll
    for (int i = 0; i < 8; i++) tot += red[i];
    const float r = rsqrtf(tot / (float)D + EPS);
    __nv_bfloat162* o2 = (__nv_bfloat162*)(out + (size_t)row * K3D + tid * 24);
    #pragma unroll
    for (int m = 0; m < 4; m++)
        trip_a_pair(o2 + 3 * m, xs[2 * m] * r * ws[2 * m], xs[2 * m + 1] * r * ws[2 * m + 1]);
}

// ---------------- softmax fp32 row -> A-style triple row ----------------
__global__ void softmax_triple_kernel(const float* __restrict__ s,
                                      __nv_bfloat16* __restrict__ out) {
    const size_t row = blockIdx.x;
    const int tid = threadIdx.x;
    __shared__ float red[8];
    const float4* p = (const float4*)(s + row * U + tid * 8);
    float4 a = p[0], b = p[1];
    float xs[8] = {a.x, a.y, a.z, a.w, b.x, b.y, b.z, b.w};

    float m = -1e30f;
    #pragma unroll
    for (int i = 0; i < 8; i++) m = fmaxf(m, xs[i]);
    #pragma unroll
    for (int o = 16; o; o >>= 1) m = fmaxf(m, __shfl_xor_sync(0xffffffffu, m, o));
    if ((tid & 31) == 0) red[tid >> 5] = m;
    __syncthreads();
    #pragma unroll
    for (int i = 0; i < 8; i++) m = fmaxf(m, red[i]);
    __syncthreads();

    float sum = 0.f;
    #pragma unroll
    for (int i = 0; i < 8; i++) { xs[i] = __expf(xs[i] - m); sum += xs[i]; }
    #pragma unroll
    for (int o = 16; o; o >>= 1) sum += __shfl_xor_sync(0xffffffffu, sum, o);
    if ((tid & 31) == 0) red[tid >> 5] = sum;
    __syncthreads();
    float tot = 0.f;
    #pragma unroll
    for (int i = 0; i < 8; i++) tot += red[i];
    const float inv = 1.0f / tot;

    __nv_bfloat162* o2 = (__nv_bfloat162*)(out + row * (size_t)K3U + tid * 24);
    #pragma unroll
    for (int q = 0; q < 4; q++)
        trip_a_pair(o2 + 3 * q, xs[2 * q] * inv, xs[2 * q + 1] * inv);
}

// ---------------- v [U,D] -> vT3 [D][3U] B-style transpose ----------------
__global__ void vtrans_kernel(const float* __restrict__ v,
                              __nv_bfloat16* __restrict__ out) {
    const int tx = threadIdx.x & 31, ty = threadIdx.x >> 5;
    const int col = blockIdx.x * 32 + tx;       // 0..D-1 -> row of vT3
    const int k0 = blockIdx.y * 64 + ty * 8;
    float xs[8];
    #pragma unroll
    for (int i = 0; i < 8; i++) xs[i] = v[(size_t)(k0 + i) * D + col];
    __nv_bfloat162* o2 = (__nv_bfloat162*)(out + (size_t)col * K3U + (size_t)k0 * 3);
    #pragma unroll
    for (int m = 0; m < 4; m++) trip_b_pair(o2 + 3 * m, xs[2 * m], xs[2 * m + 1]);
}

// ---------------- bf16 NT GEMM (K is the triple dim) ----------------------
// C[m,n] = sum_k A[m,k] * B[n,k]; A,B bf16 row-major; accum fp32.
// out_mode: 0 = fp32 Cf, 1 = triple-A to C3, 2 = triple-B to C3.
#define GBM 128
#define GBN 128
#define GBK 32
#define ASTR 40   // padded smem row stride (bf16 elems)

__global__ __launch_bounds__(256, 2)
void gemm_bf16_kernel(const __nv_bfloat16* __restrict__ A, int lda, size_t sA,
                      const __nv_bfloat16* __restrict__ B, int ldb, size_t sB,
                      float* __restrict__ Cf, __nv_bfloat16* __restrict__ C3,
                      int ldc, size_t sC, int czcol,
                      int K,
                      const float* __restrict__ bias,
                      const float* __restrict__ bias2d, int ld2,
                      const float* __restrict__ residual, int ldr,
                      float scale, int do_gelu, int out_mode) {
    __shared__ __align__(16) __nv_bfloat16 As[2][GBM * ASTR];
    __shared__ __align__(16) __nv_bfloat16 Bs[2][GBN * ASTR];

    const int z = blockIdx.z;
    A += (size_t)z * sA;
    B += (size_t)z * sB;
    if (Cf) Cf += (size_t)z * sC;
    const int colz = z * czcol;

    const int bm = blockIdx.y * GBM;
    const int bn = blockIdx.x * GBN;
    const int tid = threadIdx.x;
    const int wid = tid >> 5, lane = tid & 31;
    const int wm = wid >> 2, wn = wid & 3;      // 2 x 4 warp grid
    const int g = lane >> 2, t4 = lane & 3;

    float acc[4][4][4];
    #pragma unroll
    for (int i = 0; i < 4; i++)
        #pragma unroll
        for (int j = 0; j < 4; j++)
            #pragma unroll
            for (int c = 0; c < 4; c++) acc[i][j][c] = 0.f;

    auto loadTiles = [&](int k0, int buf) {
        #pragma unroll
        for (int it = 0; it < 2; it++) {
            int e = tid + it * 256;
            int row = e >> 2, c = e & 3;
            cp16(&As[buf][row * ASTR + c * 8],
                 A + (size_t)(bm + row) * lda + k0 + c * 8);
            cp16(&Bs[buf][row * ASTR + c * 8],
                 B + (size_t)(bn + row) * ldb + k0 + c * 8);
        }
    };

    const int nIter = K / GBK;
    loadTiles(0, 0);
    cpcommit();

    for (int it = 0; it < nIter; it++) {
        const int buf = it & 1;
        if (it + 1 < nIter) {
            loadTiles((it + 1) * GBK, buf ^ 1);
            cpcommit();
            cpwait1();
        } else {
            cpwait0();
        }
        __syncthreads();

        #pragma unroll
        for (int ks = 0; ks < 2; ks++) {
            const int kb = ks * 16;
            uint32_t afr[4][4], bfr[4][2];
            #pragma unroll
            for (int mi = 0; mi < 4; mi++) {
                const __nv_bfloat16* ab = &As[buf][(wm * 64 + mi * 16 + g) * ASTR + kb + 2 * t4];
                afr[mi][0] = *(const uint32_t*)ab;
                afr[mi][1] = *(const uint32_t*)(ab + 8 * ASTR);
                afr[mi][2] = *(const uint32_t*)(ab + 8);
                afr[mi][3] = *(const uint32_t*)(ab + 8 * ASTR + 8);
            }
            #pragma unroll
            for (int nj = 0; nj < 4; nj++) {
                const __nv_bfloat16* bb = &Bs[buf][(wn * 32 + nj * 8 + g) * ASTR + kb + 2 * t4];
                bfr[nj][0] = *(const uint32_t*)bb;
                bfr[nj][1] = *(const uint32_t*)(bb + 8);
            }
            #pragma unroll
            for (int mi = 0; mi < 4; mi++)
                #pragma unroll
                for (int nj = 0; nj < 4; nj++)
                    mma16816(acc[mi][nj], afr[mi], bfr[nj]);
        }
        __syncthreads();
    }

    // ---- epilogue ----
    #pragma unroll
    for (int mi = 0; mi < 4; mi++) {
        #pragma unroll
        for (int nj = 0; nj < 4; nj++) {
            #pragma unroll
            for (int half = 0; half < 2; half++) {
                const int row = bm + wm * 64 + mi * 16 + g + half * 8;
                const int col = bn + wn * 32 + nj * 8 + 2 * t4;
                float v0 = acc[mi][nj][half * 2 + 0] * scale;
                float v1 = acc[mi][nj][half * 2 + 1] * scale;
                if (bias)   { v0 += bias[col]; v1 += bias[col + 1]; }
                if (bias2d) { v0 += bias2d[(size_t)row * ld2 + col];
                              v1 += bias2d[(size_t)row * ld2 + col + 1]; }
                if (do_gelu) {
                    v0 = 0.5f * v0 * (1.0f + erff(v0 * 0.70710678118654752f));
                    v1 = 0.5f * v1 * (1.0f + erff(v1 * 0.70710678118654752f));
                }
                if (residual) { v0 += residual[(size_t)row * ldr + col];
                                v1 += residual[(size_t)row * ldr + col + 1]; }
                if (out_mode == 0) {
                    float2 w2; w2.x = v0; w2.y = v1;
                    *(float2*)(Cf + (size_t)row * ldc + col) = w2;
                } else {
                    const int cg = col + colz;
                    __nv_bfloat162* p = (__nv_bfloat162*)(C3 + (size_t)row * (3 * (size_t)ldc) + 3 * (size_t)cg);
                    if (out_mode == 1) trip_a_pair(p, v0, v1);
                    else               trip_b_pair(p, v0, v1);
                }
            }
        }
    }
}

// ---------------- launch ----------------
extern "C" void kernel_launch(void* const* d_in, const int* in_sizes, int n_in,
                              void* d_out, int out_size) {
    const float* x   = (const float*)d_in[0];
    const float* adj = (const float*)d_in[1];
    const float* n1w = (const float*)d_in[2];
    const float* n2w = (const float*)d_in[3];
    const float* wq  = (const float*)d_in[4];
    const float* wk  = (const float*)d_in[5];
    const float* wv  = (const float*)d_in[6];
    const float* wo  = (const float*)d_in[7];
    const float* wup = (const float*)d_in[8];
    const float* bup = (const float*)d_in[9];
    const float* wdn = (const float*)d_in[10];
    const float* bdn = (const float*)d_in[11];
    float* out = (float*)d_out;

    static float *sc = nullptr, *x2, *v;
    static __nv_bfloat16 *h3, *q3, *k3, *vT3, *attn3, *ff3,
                         *wq3, *wk3, *wv3, *wo3, *wup3, *wdn3;
    if (!sc) {
        cudaGetSymbolAddress((void**)&sc, g_scores);
        cudaGetSymbolAddress((void**)&x2, g_x2);
        cudaGetSymbolAddress((void**)&v,  g_v);
        cudaGetSymbolAddress((void**)&h3, g_h3);
        cudaGetSymbolAddress((void**)&q3, g_q3);
        cudaGetSymbolAddress((void**)&k3, g_k3);
        cudaGetSymbolAddress((void**)&vT3, g_vT3);
        cudaGetSymbolAddress((void**)&attn3, g_attn3);
        cudaGetSymbolAddress((void**)&ff3, g_ff3);
        cudaGetSymbolAddress((void**)&wq3, g_wq3);
        cudaGetSymbolAddress((void**)&wk3, g_wk3);
        cudaGetSymbolAddress((void**)&wv3, g_wv3);
        cudaGetSymbolAddress((void**)&wo3, g_wo3);
        cudaGetSymbolAddress((void**)&wup3, g_wup3);
        cudaGetSymbolAddress((void**)&wdn3, g_wdn3);
    }

    const float attn_scale = 0.08838834764831845f; // 1/sqrt(128)

    // --- weight conversions (B-style triples) ---
    {
        size_t n8 = (size_t)D * D / 8;          // 524288
        int blks = (int)(n8 / 256);
        conv_triple_kernel<<<blks, 256>>>(wq, wq3, n8, 1);
        conv_triple_kernel<<<blks, 256>>>(wk, wk3, n8, 1);
        conv_triple_kernel<<<blks, 256>>>(wv, wv3, n8, 1);
        conv_triple_kernel<<<blks, 256>>>(wo, wo3, n8, 1);
        size_t n8f = (size_t)D_FF * D / 8;
        int blksf = (int)(n8f / 256);
        conv_triple_kernel<<<blksf, 256>>>(wup, wup3, n8f, 1);
        conv_triple_kernel<<<blksf, 256>>>(wdn, wdn3, n8f, 1);
    }

    // 1) h3 = triple(rmsnorm(x, n1w))
    rmsnorm_triple_kernel<<<U, 256>>>(x, n1w, h3);

    // 2-4) q3 (triple-A), k3 (triple-B), v (fp32)
    dim3 gDD(D / GBN, U / GBM, 1);
    gemm_bf16_kernel<<<gDD, 256>>>(h3, K3D, 0, wq3, K3D, 0,
                                   nullptr, q3, D, 0, 0, K3D,
                                   nullptr, nullptr, 0, nullptr, 0, 1.0f, 0, 1);
    gemm_bf16_kernel<<<gDD, 256>>>(h3, K3D, 0, wk3, K3D, 0,
                                   nullptr, k3, D, 0, 0, K3D,
                                   nullptr, nullptr, 0, nullptr, 0, 1.0f, 0, 2);
    gemm_bf16_kernel<<<gDD, 256>>>(h3, K3D, 0, wv3, K3D, 0,
                                   v, nullptr, D, 0, 0, K3D,
                                   nullptr, nullptr, 0, nullptr, 0, 1.0f, 0, 0);

    // v -> vT3 (B-style, transposed)
    vtrans_kernel<<<dim3(D / 32, U / 64), 256>>>(v, vT3);

    // 5) scores[z] = q_z k_z^T * scale + adj  (fp32)
    dim3 gS(U / GBN, U / GBM, N_HEADS);
    gemm_bf16_kernel<<<gS, 256>>>(q3, K3D, (size_t)K3H,
                                  k3, K3D, (size_t)K3H,
                                  sc, nullptr, U, (size_t)U * U, 0, K3H,
                                  nullptr, adj, U, nullptr, 0, attn_scale, 0, 0);

    // 6) softmax rows -> attn3 (triple-A)
    softmax_triple_kernel<<<N_HEADS * U, 256>>>(sc, attn3);

    // 7) ao3 (reuse h3) = attn3 @ vT3^T  -> triple-A, per-head col slices
    dim3 gPV(D_HEAD / GBN, U / GBM, N_HEADS);
    gemm_bf16_kernel<<<gPV, 256>>>(attn3, K3U, (size_t)U * K3U,
                                   vT3, K3U, (size_t)D_HEAD * K3U,
                                   nullptr, h3, D, 0, D_HEAD, K3U,
                                   nullptr, nullptr, 0, nullptr, 0, 1.0f, 0, 1);

    // 8) x2 = x + ao @ wo^T (fp32)
    gemm_bf16_kernel<<<gDD, 256>>>(h3, K3D, 0, wo3, K3D, 0,
                                   x2, nullptr, D, 0, 0, K3D,
                                   nullptr, nullptr, 0, x, D, 1.0f, 0, 0);

    // 9) h3 = triple(rmsnorm(x2, n2w))
    rmsnorm_triple_kernel<<<U, 256>>>(x2, n2w, h3);

    // 10) ff3 = triple-A(gelu(h2 @ wup^T + bup))
    dim3 gUP(D_FF / GBN, U / GBM, 1);
    gemm_bf16_kernel<<<gUP, 256>>>(h3, K3D, 0, wup3, K3D, 0,
                                   nullptr, ff3, D_FF, 0, 0, K3D,
                                   bup, nullptr, 0, nullptr, 0, 1.0f, 1, 1);

    // 11) out = x2 + ff @ wdn^T + bdn (fp32)
    dim3 gDN(D / GBN, U / GBM, 1);
    gemm_bf16_kernel<<<gDN, 256>>>(ff3, K3F, 0, wdn3, K3F, 0,
                                   out, nullptr, D, 0, 0, K3F,
                                   bdn, nullptr, 0, x2, D, 1.0f, 0, 0);
}

// round 5
// speedup vs baseline: 1.9937x; 1.1363x over previous
#include <cuda_runtime.h>
#include <cuda_bf16.h>
#include <math.h>
#include <stdint.h>

#define U 2048
#define D 2048
#define N_HEADS 16
#define D_HEAD 128
#define D_FF 8192
#define EPS 1e-6f

#define K3D (3*D)       // 6144
#define K3H (3*D_HEAD)  // 384
#define K3F (3*D_FF)    // 24576
#define K3U (3*U)       // 6144

// tcgen05 availability: only when compiling an arch-specific ('a') target.
#if !defined(__CUDA_ARCH__) || defined(__CUDA_ARCH_FEAT_SM103_ALL) || defined(__CUDA_ARCH_FEAT_SM100_ALL) || defined(__CUDA_ARCH_FEAT_SM101_ALL) || defined(__CUDA_ARCH_FEAT_SM110_ALL)
#define HAS_TCG 1
#else
#define HAS_TCG 0
#endif

// ---------------- scratch (device globals: allocation-free) ----------------
__device__ float g_scores[(size_t)N_HEADS * U * U];
__device__ float g_x2[(size_t)U * D];
__device__ float g_v[(size_t)U * D];
__device__ __nv_bfloat16 g_h3 [(size_t)U * K3D];
__device__ __nv_bfloat16 g_q3 [(size_t)U * K3D];
__device__ __nv_bfloat16 g_k3 [(size_t)U * K3D];
__device__ __nv_bfloat16 g_vT3[(size_t)D * K3U];
__device__ __nv_bfloat16 g_attn3[(size_t)N_HEADS * U * K3U];
__device__ __nv_bfloat16 g_ff3[(size_t)U * K3F];
__device__ __nv_bfloat16 g_wq3[(size_t)D * K3D];
__device__ __nv_bfloat16 g_wk3[(size_t)D * K3D];
__device__ __nv_bfloat16 g_wv3[(size_t)D * K3D];
__device__ __nv_bfloat16 g_wo3[(size_t)D * K3D];
__device__ __nv_bfloat16 g_wup3[(size_t)D_FF * K3D];
__device__ __nv_bfloat16 g_wdn3[(size_t)D * K3F];

// ---------------- helpers ----------------
__device__ __forceinline__ void split2(float x, __nv_bfloat16& hi, __nv_bfloat16& lo) {
    hi = __float2bfloat16(x);
    lo = __float2bfloat16(x - __bfloat162float(hi));
}
__device__ __forceinline__ __nv_bfloat162 mk2(__nv_bfloat16 a, __nv_bfloat16 b) {
    __nv_bfloat162 r; r.x = a; r.y = b; return r;
}
__device__ __forceinline__ void trip_a_pair(__nv_bfloat162* p, float x0, float x1) {
    __nv_bfloat16 h0, l0, h1, l1; split2(x0, h0, l0); split2(x1, h1, l1);
    p[0] = mk2(h0, l0); p[1] = mk2(h0, h1); p[2] = mk2(l1, h1);
}
__device__ __forceinline__ void trip_b_pair(__nv_bfloat162* p, float x0, float x1) {
    __nv_bfloat16 h0, l0, h1, l1; split2(x0, h0, l0); split2(x1, h1, l1);
    p[0] = mk2(h0, h0); p[1] = mk2(l0, h1); p[2] = mk2(h1, l1);
}

__device__ __forceinline__ void cp16(void* smem, const void* gmem) {
    uint32_t s = (uint32_t)__cvta_generic_to_shared(smem);
    asm volatile("cp.async.ca.shared.global [%0], [%1], 16;\n" :: "r"(s), "l"(gmem));
}
__device__ __forceinline__ void cpcommit() { asm volatile("cp.async.commit_group;\n"); }
__device__ __forceinline__ void cpwait0() { asm volatile("cp.async.wait_group 0;\n"); }
__device__ __forceinline__ void cpwait1() { asm volatile("cp.async.wait_group 1;\n"); }

__device__ __forceinline__ void mma16816(float* c, const uint32_t* a, const uint32_t* b) {
    asm volatile(
        "mma.sync.aligned.m16n8k16.row.col.f32.bf16.bf16.f32 "
        "{%0,%1,%2,%3}, {%4,%5,%6,%7}, {%8,%9}, {%0,%1,%2,%3};\n"
        : "+f"(c[0]), "+f"(c[1]), "+f"(c[2]), "+f"(c[3])
        : "r"(a[0]), "r"(a[1]), "r"(a[2]), "r"(a[3]), "r"(b[0]), "r"(b[1]));
}

// ---------------- shared tiling params ----------------
#define GBM 128
#define GBN 128
#define GBK 32
#define ASTR 40

#if HAS_TCG
// ---------------- tcgen05 helpers ----------------
__device__ __forceinline__ uint32_t elect_one_pred() {
    uint32_t pred;
    asm volatile(
        "{\n\t.reg .pred p;\n\telect.sync _|p, 0xFFFFFFFF;\n\tselp.b32 %0, 1, 0, p;\n\t}"
        : "=r"(pred));
    return pred;
}
#define TCG_ALLOC(dst, n)  asm volatile("tcgen05.alloc.cta_group::1.sync.aligned.shared::cta.b32 [%0], %1;" :: "r"(dst), "r"(n) : "memory")
#define TCG_DEALLOC(t, n)  asm volatile("tcgen05.dealloc.cta_group::1.sync.aligned.b32 %0, %1;" :: "r"(t), "r"(n))
#define TCG_COMMIT(mb)     asm volatile("tcgen05.commit.cta_group::1.mbarrier::arrive::one.shared::cluster.b64 [%0];" :: "r"(mb) : "memory")
#define TCG_FENCE_AFTER()  asm volatile("tcgen05.fence::after_thread_sync;" ::: "memory")
#define TCG_FENCE_BEFORE() asm volatile("tcgen05.fence::before_thread_sync;" ::: "memory")
#define TCG_WAIT_LD()      asm volatile("tcgen05.wait::ld.sync.aligned;" ::: "memory")
#define FENCE_ASYNC_SHARED() asm volatile("fence.proxy.async.shared::cta;" ::: "memory")
#define MBAR_INIT(mb, c)   asm volatile("mbarrier.init.shared.b64 [%0], %1;" :: "r"(mb), "r"(c) : "memory")

__device__ __forceinline__ void mbar_wait_parity(uint32_t mbar, uint32_t parity) {
    uint32_t done;
    asm volatile(
        "{\n\t.reg .pred p;\n\t"
        "mbarrier.try_wait.parity.acquire.cta.shared::cta.b64 p, [%1], %2;\n\t"
        "selp.b32 %0, 1, 0, p;\n\t}"
        : "=r"(done) : "r"(mbar), "r"(parity) : "memory");
    if (!done) {
        asm volatile(
            "{\n\t.reg .pred P1;\n\t"
            "WAIT_LOOP_%=:\n\t"
            "mbarrier.try_wait.parity.acquire.cta.shared::cta.b64 P1, [%0], %1, 0x989680;\n\t"
            "@P1 bra.uni WAIT_DONE_%=;\n\t"
            "bra.uni WAIT_LOOP_%=;\n\t"
            "WAIT_DONE_%=:\n\t}"
            :: "r"(mbar), "r"(parity) : "memory");
    }
}

__device__ __forceinline__ void tcg_ld_x32(uint32_t* r, uint32_t taddr) {
    asm volatile(
        "tcgen05.ld.sync.aligned.32x32b.x32.b32 "
        "{%0,%1,%2,%3,%4,%5,%6,%7,%8,%9,%10,%11,%12,%13,%14,%15,"
        "%16,%17,%18,%19,%20,%21,%22,%23,%24,%25,%26,%27,%28,%29,%30,%31}, [%32];"
        : "=r"(r[0]), "=r"(r[1]), "=r"(r[2]), "=r"(r[3]), "=r"(r[4]), "=r"(r[5]),
          "=r"(r[6]), "=r"(r[7]), "=r"(r[8]), "=r"(r[9]), "=r"(r[10]), "=r"(r[11]),
          "=r"(r[12]), "=r"(r[13]), "=r"(r[14]), "=r"(r[15]), "=r"(r[16]), "=r"(r[17]),
          "=r"(r[18]), "=r"(r[19]), "=r"(r[20]), "=r"(r[21]), "=r"(r[22]), "=r"(r[23]),
          "=r"(r[24]), "=r"(r[25]), "=r"(r[26]), "=r"(r[27]), "=r"(r[28]), "=r"(r[29]),
          "=r"(r[30]), "=r"(r[31])
        : "r"(taddr));
}

__device__ __forceinline__ void tcg_mma_f16_ss(uint32_t d, uint64_t ad, uint64_t bd,
                                               uint32_t idesc, uint32_t en) {
    asm volatile(
        "{\n\t.reg .pred p;\n\tsetp.ne.u32 p, %5, 0;\n\t"
        "tcgen05.mma.cta_group::1.kind::f16 [%0], %1, %2, %3, {%4,%4,%4,%4}, p;\n\t}"
        :: "r"(d), "l"(ad), "l"(bd), "r"(idesc), "r"(0u), "r"(en) : "memory");
}

// SW128 smem descriptor: layout=2, version=1, SBO=64, LBO=1
#define SMEM_DESC_BASE ( (uint64_t(2) << 61) | (uint64_t(1) << 46) \
                       | (uint64_t(64) << 32) | (uint64_t(1) << 16) )
#define MK_DESC(addr) (SMEM_DESC_BASE | ((uint64_t)((addr) >> 4) & 0x3FFF))
#endif // HAS_TCG

#define SWZ(o) ((o) ^ (((o) >> 3) & 0x70))

// ================= big-GEMM kernel: C[m,n] = sum_k A[m,k]*B[n,k] ===========
// Tile M=128 x N=256. tcgen05 path on 'a' targets, mma.sync fallback else.
// out_mode: 0 fp32, 1 triple-A, 2 triple-B.
#define TCG_TN 256
#define TCG_IDESC 0x8400490u   // F32 acc, bf16 x bf16, N=256, M=128
#define ST_A 16384
#define ST_B 32768
#define OFF_A(s) (1024 + (s) * ST_A)
#define OFF_B(s) (1024 + 3 * ST_A + (s) * ST_B)
#define TCG_SMEM (1024 + 3 * ST_A + 3 * ST_B)   // 148480

extern __shared__ char tcg_smem[];

__global__ __launch_bounds__(256, 1)
void tcg_gemm_kernel(const __nv_bfloat16* __restrict__ A, int lda,
                     const __nv_bfloat16* __restrict__ B, int ldb,
                     float* __restrict__ Cf, __nv_bfloat16* __restrict__ C3,
                     int ldc, int K,
                     const float* __restrict__ bias,
                     const float* __restrict__ residual, int ldr,
                     int do_gelu, int out_mode) {
#if HAS_TCG
    const uint32_t smem_base = (uint32_t)__cvta_generic_to_shared(tcg_smem);
    const int tid = threadIdx.x;
    const int wid = tid >> 5, lane = tid & 31;
    const int bm = blockIdx.y * 128;
    const int bn = blockIdx.x * TCG_TN;

    if (wid == 0) TCG_ALLOC(smem_base, 512);
    if (tid == 0) {
        MBAR_INIT(smem_base + 8,  1);
        MBAR_INIT(smem_base + 16, 1);
        MBAR_INIT(smem_base + 24, 1);
    }
    __syncthreads();
    uint32_t tmem_base;
    asm volatile("ld.shared.b32 %0, [%1];" : "=r"(tmem_base) : "r"(smem_base));

    auto load_stage = [&](int s, int k0) {
        char* sa = tcg_smem + OFF_A(s);
        char* sb = tcg_smem + OFF_B(s);
        #pragma unroll
        for (int i = 0; i < 4; i++) {
            int c = i * 256 + tid;
            int row = c >> 3, sub = c & 7;
            cp16(sa + SWZ(row * 128 + sub * 16),
                 A + (size_t)(bm + row) * lda + k0 + sub * 8);
        }
        #pragma unroll
        for (int i = 0; i < 8; i++) {
            int c = i * 256 + tid;
            int row = c >> 3, sub = c & 7;
            cp16(sb + SWZ(row * 128 + sub * 16),
                 B + (size_t)(bn + row) * ldb + k0 + sub * 8);
        }
    };

    const int nIter = K / 64;

    load_stage(0, 0);  cpcommit();
    load_stage(1, 64); cpcommit();

    for (int it = 0; it < nIter; it++) {
        const int s = it % 3;
        if (it + 1 < nIter) cpwait1(); else cpwait0();
        __syncthreads();

        if (wid == 0) {
            if (elect_one_pred()) {
                FENCE_ASYNC_SHARED();
                uint64_t ad = MK_DESC(smem_base + OFF_A(s));
                uint64_t bd = MK_DESC(smem_base + OFF_B(s));
                #pragma unroll
                for (int ks = 0; ks < 4; ks++)
                    tcg_mma_f16_ss(tmem_base, ad + ks * 2, bd + ks * 2,
                                   TCG_IDESC, (it > 0 || ks > 0) ? 1u : 0u);
                TCG_COMMIT(smem_base + 8 + s * 8);
            }
        }

        if (it + 2 < nIter) {
            const int sl = (it + 2) % 3;
            if (it + 2 >= 3) {
                const int n = (it + 2) / 3;
                mbar_wait_parity(smem_base + 8 + sl * 8, (uint32_t)((n - 1) & 1));
            }
            load_stage(sl, (it + 2) * 64);
            cpcommit();
        }
    }

    {
        const int sl = (nIter - 1) % 3;
        const int n = (nIter - 1) / 3 + 1;
        mbar_wait_parity(smem_base + 8 + sl * 8, (uint32_t)((n - 1) & 1));
    }
    TCG_FENCE_AFTER();

    const int row = bm + (wid & 3) * 32 + lane;
    const int colbase = (wid >> 2) * 128;
    #pragma unroll
    for (int ch = 0; ch < 4; ch++) {
        const int c0 = colbase + ch * 32;
        uint32_t r[32];
        tcg_ld_x32(r, tmem_base + c0);
        TCG_WAIT_LD();
        #pragma unroll
        for (int j = 0; j < 32; j += 2) {
            const int col = bn + c0 + j;
            float v0 = __uint_as_float(r[j]);
            float v1 = __uint_as_float(r[j + 1]);
            if (bias)     { v0 += bias[col]; v1 += bias[col + 1]; }
            if (do_gelu) {
                v0 = 0.5f * v0 * (1.0f + erff(v0 * 0.70710678118654752f));
                v1 = 0.5f * v1 * (1.0f + erff(v1 * 0.70710678118654752f));
            }
            if (residual) { v0 += residual[(size_t)row * ldr + col];
                            v1 += residual[(size_t)row * ldr + col + 1]; }
            if (out_mode == 0) {
                float2 w2; w2.x = v0; w2.y = v1;
                *(float2*)(Cf + (size_t)row * ldc + col) = w2;
            } else {
                __nv_bfloat162* p = (__nv_bfloat162*)(C3 + (size_t)row * (3 * (size_t)ldc) + 3 * (size_t)col);
                if (out_mode == 1) trip_a_pair(p, v0, v1);
                else               trip_b_pair(p, v0, v1);
            }
        }
    }

    TCG_FENCE_BEFORE();
    __syncthreads();
    if (wid == 0) TCG_DEALLOC(tmem_base, 512);

#else  // ---------------- mma.sync fallback (non-'a' target) ----------------
    __nv_bfloat16* As = (__nv_bfloat16*)tcg_smem;           // [2][GBM*ASTR]
    __nv_bfloat16* Bs = As + 2 * GBM * ASTR;                // [2][GBN*ASTR]
    const int tid = threadIdx.x;
    const int wid = tid >> 5, lane = tid & 31;
    const int wm = wid >> 2, wn = wid & 3;
    const int g = lane >> 2, t4 = lane & 3;
    const int bm = blockIdx.y * 128;

    for (int halfn = 0; halfn < 2; halfn++) {
        const int bn = blockIdx.x * TCG_TN + halfn * 128;

        float acc[4][4][4];
        #pragma unroll
        for (int i = 0; i < 4; i++)
            #pragma unroll
            for (int j = 0; j < 4; j++)
                #pragma unroll
                for (int c = 0; c < 4; c++) acc[i][j][c] = 0.f;

        auto loadTiles = [&](int k0, int buf) {
            #pragma unroll
            for (int it2 = 0; it2 < 2; it2++) {
                int e = tid + it2 * 256;
                int rw = e >> 2, c = e & 3;
                cp16(&As[buf * GBM * ASTR + rw * ASTR + c * 8],
                     A + (size_t)(bm + rw) * lda + k0 + c * 8);
                cp16(&Bs[buf * GBN * ASTR + rw * ASTR + c * 8],
                     B + (size_t)(bn + rw) * ldb + k0 + c * 8);
            }
        };

        const int nIter = K / GBK;
        loadTiles(0, 0);
        cpcommit();

        for (int it = 0; it < nIter; it++) {
            const int buf = it & 1;
            if (it + 1 < nIter) { loadTiles((it + 1) * GBK, buf ^ 1); cpcommit(); cpwait1(); }
            else cpwait0();
            __syncthreads();

            #pragma unroll
            for (int ks = 0; ks < 2; ks++) {
                const int kb = ks * 16;
                uint32_t afr[4][4], bfr[4][2];
                #pragma unroll
                for (int mi = 0; mi < 4; mi++) {
                    const __nv_bfloat16* ab = &As[buf * GBM * ASTR + (wm * 64 + mi * 16 + g) * ASTR + kb + 2 * t4];
                    afr[mi][0] = *(const uint32_t*)ab;
                    afr[mi][1] = *(const uint32_t*)(ab + 8 * ASTR);
                    afr[mi][2] = *(const uint32_t*)(ab + 8);
                    afr[mi][3] = *(const uint32_t*)(ab + 8 * ASTR + 8);
                }
                #pragma unroll
                for (int nj = 0; nj < 4; nj++) {
                    const __nv_bfloat16* bb = &Bs[buf * GBN * ASTR + (wn * 32 + nj * 8 + g) * ASTR + kb + 2 * t4];
                    bfr[nj][0] = *(const uint32_t*)bb;
                    bfr[nj][1] = *(const uint32_t*)(bb + 8);
                }
                #pragma unroll
                for (int mi = 0; mi < 4; mi++)
                    #pragma unroll
                    for (int nj = 0; nj < 4; nj++)
                        mma16816(acc[mi][nj], afr[mi], bfr[nj]);
            }
            __syncthreads();
        }

        #pragma unroll
        for (int mi = 0; mi < 4; mi++)
            #pragma unroll
            for (int nj = 0; nj < 4; nj++)
                #pragma unroll
                for (int half = 0; half < 2; half++) {
                    const int row = bm + wm * 64 + mi * 16 + g + half * 8;
                    const int col = bn + wn * 32 + nj * 8 + 2 * t4;
                    float v0 = acc[mi][nj][half * 2 + 0];
                    float v1 = acc[mi][nj][half * 2 + 1];
                    if (bias)     { v0 += bias[col]; v1 += bias[col + 1]; }
                    if (do_gelu) {
                        v0 = 0.5f * v0 * (1.0f + erff(v0 * 0.70710678118654752f));
                        v1 = 0.5f * v1 * (1.0f + erff(v1 * 0.70710678118654752f));
                    }
                    if (residual) { v0 += residual[(size_t)row * ldr + col];
                                    v1 += residual[(size_t)row * ldr + col + 1]; }
                    if (out_mode == 0) {
                        float2 w2; w2.x = v0; w2.y = v1;
                        *(float2*)(Cf + (size_t)row * ldc + col) = w2;
                    } else {
                        __nv_bfloat162* p = (__nv_bfloat162*)(C3 + (size_t)row * (3 * (size_t)ldc) + 3 * (size_t)col);
                        if (out_mode == 1) trip_a_pair(p, v0, v1);
                        else               trip_b_pair(p, v0, v1);
                    }
                }
        __syncthreads();
    }
#endif
}

// ---------------- triple conversion (fp32 [R,C] -> bf16 [R,3C]) ------------
__global__ void conv_triple_kernel(const float* __restrict__ in,
                                   __nv_bfloat16* __restrict__ out,
                                   size_t n8, int styleB) {
    size_t g = (size_t)blockIdx.x * 256 + threadIdx.x;
    if (g >= n8) return;
    const float4* p = (const float4*)(in + g * 8);
    float4 a = p[0], b = p[1];
    float xs[8] = {a.x, a.y, a.z, a.w, b.x, b.y, b.z, b.w};
    __nv_bfloat162* o = (__nv_bfloat162*)(out + g * 24);
    if (styleB) {
        #pragma unroll
        for (int m = 0; m < 4; m++) trip_b_pair(o + 3 * m, xs[2 * m], xs[2 * m + 1]);
    } else {
        #pragma unroll
        for (int m = 0; m < 4; m++) trip_a_pair(o + 3 * m, xs[2 * m], xs[2 * m + 1]);
    }
}

// ---------------- RMSNorm -> A-style triple ----------------
__global__ void rmsnorm_triple_kernel(const float* __restrict__ x,
                                      const float* __restrict__ w,
                                      __nv_bfloat16* __restrict__ out) {
    const int row = blockIdx.x;
    const int tid = threadIdx.x;
    __shared__ float red[8];
    const float4* xr = (const float4*)(x + (size_t)row * D + tid * 8);
    const float4* wr = (const float4*)(w + tid * 8);
    float4 xa = xr[0], xb = xr[1];
    float4 wa = wr[0], wb = wr[1];
    float xs[8] = {xa.x, xa.y, xa.z, xa.w, xb.x, xb.y, xb.z, xb.w};
    float ws[8] = {wa.x, wa.y, wa.z, wa.w, wb.x, wb.y, wb.z, wb.w};
    float ss = 0.f;
    #pragma unroll
    for (int i = 0; i < 8; i++) ss += xs[i] * xs[i];
    #pragma unroll
    for (int o = 16; o; o >>= 1) ss += __shfl_xor_sync(0xffffffffu, ss, o);
    if ((tid & 31) == 0) red[tid >> 5] = ss;
    __syncthreads();
    float tot = 0.f;
    #pragma unroll
    for (int i = 0; i < 8; i++) tot += red[i];
    const float r = rsqrtf(tot / (float)D + EPS);
    __nv_bfloat162* o2 = (__nv_bfloat162*)(out + (size_t)row * K3D + tid * 24);
    #pragma unroll
    for (int m = 0; m < 4; m++)
        trip_a_pair(o2 + 3 * m, xs[2 * m] * r * ws[2 * m], xs[2 * m + 1] * r * ws[2 * m + 1]);
}

// ---------------- softmax fp32 row -> A-style triple row ----------------
__global__ void softmax_triple_kernel(const float* __restrict__ s,
                                      __nv_bfloat16* __restrict__ out) {
    const size_t row = blockIdx.x;
    const int tid = threadIdx.x;
    __shared__ float red[8];
    const float4* p = (const float4*)(s + row * U + tid * 8);
    float4 a = p[0], b = p[1];
    float xs[8] = {a.x, a.y, a.z, a.w, b.x, b.y, b.z, b.w};

    float m = -1e30f;
    #pragma unroll
    for (int i = 0; i < 8; i++) m = fmaxf(m, xs[i]);
    #pragma unroll
    for (int o = 16; o; o >>= 1) m = fmaxf(m, __shfl_xor_sync(0xffffffffu, m, o));
    if ((tid & 31) == 0) red[tid >> 5] = m;
    __syncthreads();
    #pragma unroll
    for (int i = 0; i < 8; i++) m = fmaxf(m, red[i]);
    __syncthreads();

    float sum = 0.f;
    #pragma unroll
    for (int i = 0; i < 8; i++) { xs[i] = __expf(xs[i] - m); sum += xs[i]; }
    #pragma unroll
    for (int o = 16; o; o >>= 1) sum += __shfl_xor_sync(0xffffffffu, sum, o);
    if ((tid & 31) == 0) red[tid >> 5] = sum;
    __syncthreads();
    float tot = 0.f;
    #pragma unroll
    for (int i = 0; i < 8; i++) tot += red[i];
    const float inv = 1.0f / tot;

    __nv_bfloat162* o2 = (__nv_bfloat162*)(out + row * (size_t)K3U + tid * 24);
    #pragma unroll
    for (int q = 0; q < 4; q++)
        trip_a_pair(o2 + 3 * q, xs[2 * q] * inv, xs[2 * q + 1] * inv);
}

// ---------------- v [U,D] -> vT3 [D][3U] B-style transpose ----------------
__global__ void vtrans_kernel(const float* __restrict__ v,
                              __nv_bfloat16* __restrict__ out) {
    const int tx = threadIdx.x & 31, ty = threadIdx.x >> 5;
    const int col = blockIdx.x * 32 + tx;
    const int k0 = blockIdx.y * 64 + ty * 8;
    float xs[8];
    #pragma unroll
    for (int i = 0; i < 8; i++) xs[i] = v[(size_t)(k0 + i) * D + col];
    __nv_bfloat162* o2 = (__nv_bfloat162*)(out + (size_t)col * K3U + (size_t)k0 * 3);
    #pragma unroll
    for (int m = 0; m < 4; m++) trip_b_pair(o2 + 3 * m, xs[2 * m], xs[2 * m + 1]);
}

// ---------------- mma.sync NT GEMM (scores / PV) ---------------------------
__global__ __launch_bounds__(256, 2)
void gemm_bf16_kernel(const __nv_bfloat16* __restrict__ A, int lda, size_t sA,
                      const __nv_bfloat16* __restrict__ B, int ldb, size_t sB,
                      float* __restrict__ Cf, __nv_bfloat16* __restrict__ C3,
                      int ldc, size_t sC, int czcol,
                      int K,
                      const float* __restrict__ bias,
                      const float* __restrict__ bias2d, int ld2,
                      const float* __restrict__ residual, int ldr,
                      float scale, int do_gelu, int out_mode) {
    __shared__ __align__(16) __nv_bfloat16 As[2][GBM * ASTR];
    __shared__ __align__(16) __nv_bfloat16 Bs[2][GBN * ASTR];

    const int z = blockIdx.z;
    A += (size_t)z * sA;
    B += (size_t)z * sB;
    if (Cf) Cf += (size_t)z * sC;
    const int colz = z * czcol;

    const int bm = blockIdx.y * GBM;
    const int bn = blockIdx.x * GBN;
    const int tid = threadIdx.x;
    const int wid = tid >> 5, lane = tid & 31;
    const int wm = wid >> 2, wn = wid & 3;
    const int g = lane >> 2, t4 = lane & 3;

    float acc[4][4][4];
    #pragma unroll
    for (int i = 0; i < 4; i++)
        #pragma unroll
        for (int j = 0; j < 4; j++)
            #pragma unroll
            for (int c = 0; c < 4; c++) acc[i][j][c] = 0.f;

    auto loadTiles = [&](int k0, int buf) {
        #pragma unroll
        for (int it = 0; it < 2; it++) {
            int e = tid + it * 256;
            int row = e >> 2, c = e & 3;
            cp16(&As[buf][row * ASTR + c * 8],
                 A + (size_t)(bm + row) * lda + k0 + c * 8);
            cp16(&Bs[buf][row * ASTR + c * 8],
                 B + (size_t)(bn + row) * ldb + k0 + c * 8);
        }
    };

    const int nIter = K / GBK;
    loadTiles(0, 0);
    cpcommit();

    for (int it = 0; it < nIter; it++) {
        const int buf = it & 1;
        if (it + 1 < nIter) {
            loadTiles((it + 1) * GBK, buf ^ 1);
            cpcommit();
            cpwait1();
        } else {
            cpwait0();
        }
        __syncthreads();

        #pragma unroll
        for (int ks = 0; ks < 2; ks++) {
            const int kb = ks * 16;
            uint32_t afr[4][4], bfr[4][2];
            #pragma unroll
            for (int mi = 0; mi < 4; mi++) {
                const __nv_bfloat16* ab = &As[buf][(wm * 64 + mi * 16 + g) * ASTR + kb + 2 * t4];
                afr[mi][0] = *(const uint32_t*)ab;
                afr[mi][1] = *(const uint32_t*)(ab + 8 * ASTR);
                afr[mi][2] = *(const uint32_t*)(ab + 8);
                afr[mi][3] = *(const uint32_t*)(ab + 8 * ASTR + 8);
            }
            #pragma unroll
            for (int nj = 0; nj < 4; nj++) {
                const __nv_bfloat16* bb = &Bs[buf][(wn * 32 + nj * 8 + g) * ASTR + kb + 2 * t4];
                bfr[nj][0] = *(const uint32_t*)bb;
                bfr[nj][1] = *(const uint32_t*)(bb + 8);
            }
            #pragma unroll
            for (int mi = 0; mi < 4; mi++)
                #pragma unroll
                for (int nj = 0; nj < 4; nj++)
                    mma16816(acc[mi][nj], afr[mi], bfr[nj]);
        }
        __syncthreads();
    }

    #pragma unroll
    for (int mi = 0; mi < 4; mi++) {
        #pragma unroll
        for (int nj = 0; nj < 4; nj++) {
            #pragma unroll
            for (int half = 0; half < 2; half++) {
                const int row = bm + wm * 64 + mi * 16 + g + half * 8;
                const int col = bn + wn * 32 + nj * 8 + 2 * t4;
                float v0 = acc[mi][nj][half * 2 + 0] * scale;
                float v1 = acc[mi][nj][half * 2 + 1] * scale;
                if (bias)   { v0 += bias[col]; v1 += bias[col + 1]; }
                if (bias2d) { v0 += bias2d[(size_t)row * ld2 + col];
                              v1 += bias2d[(size_t)row * ld2 + col + 1]; }
                if (do_gelu) {
                    v0 = 0.5f * v0 * (1.0f + erff(v0 * 0.70710678118654752f));
                    v1 = 0.5f * v1 * (1.0f + erff(v1 * 0.70710678118654752f));
                }
                if (residual) { v0 += residual[(size_t)row * ldr + col];
                                v1 += residual[(size_t)row * ldr + col + 1]; }
                if (out_mode == 0) {
                    float2 w2; w2.x = v0; w2.y = v1;
                    *(float2*)(Cf + (size_t)row * ldc + col) = w2;
                } else {
                    const int cg = col + colz;
                    __nv_bfloat162* p = (__nv_bfloat162*)(C3 + (size_t)row * (3 * (size_t)ldc) + 3 * (size_t)cg);
                    if (out_mode == 1) trip_a_pair(p, v0, v1);
                    else               trip_b_pair(p, v0, v1);
                }
            }
        }
    }
}

// ---------------- launch ----------------
extern "C" void kernel_launch(void* const* d_in, const int* in_sizes, int n_in,
                              void* d_out, int out_size) {
    const float* x   = (const float*)d_in[0];
    const float* adj = (const float*)d_in[1];
    const float* n1w = (const float*)d_in[2];
    const float* n2w = (const float*)d_in[3];
    const float* wq  = (const float*)d_in[4];
    const float* wk  = (const float*)d_in[5];
    const float* wv  = (const float*)d_in[6];
    const float* wo  = (const float*)d_in[7];
    const float* wup = (const float*)d_in[8];
    const float* bup = (const float*)d_in[9];
    const float* wdn = (const float*)d_in[10];
    const float* bdn = (const float*)d_in[11];
    float* out = (float*)d_out;

    static float *sc = nullptr, *x2, *v;
    static __nv_bfloat16 *h3, *q3, *k3, *vT3, *attn3, *ff3,
                         *wq3, *wk3, *wv3, *wo3, *wup3, *wdn3;
    static bool attr_done = false;
    if (!sc) {
        cudaGetSymbolAddress((void**)&sc, g_scores);
        cudaGetSymbolAddress((void**)&x2, g_x2);
        cudaGetSymbolAddress((void**)&v,  g_v);
        cudaGetSymbolAddress((void**)&h3, g_h3);
        cudaGetSymbolAddress((void**)&q3, g_q3);
        cudaGetSymbolAddress((void**)&k3, g_k3);
        cudaGetSymbolAddress((void**)&vT3, g_vT3);
        cudaGetSymbolAddress((void**)&attn3, g_attn3);
        cudaGetSymbolAddress((void**)&ff3, g_ff3);
        cudaGetSymbolAddress((void**)&wq3, g_wq3);
        cudaGetSymbolAddress((void**)&wk3, g_wk3);
        cudaGetSymbolAddress((void**)&wv3, g_wv3);
        cudaGetSymbolAddress((void**)&wo3, g_wo3);
        cudaGetSymbolAddress((void**)&wup3, g_wup3);
        cudaGetSymbolAddress((void**)&wdn3, g_wdn3);
    }
    if (!attr_done) {
        cudaFuncSetAttribute(tcg_gemm_kernel,
                             cudaFuncAttributeMaxDynamicSharedMemorySize, TCG_SMEM);
        attr_done = true;
    }

    const float attn_scale = 0.08838834764831845f; // 1/sqrt(128)

    // --- weight conversions (B-style triples) ---
    {
        size_t n8 = (size_t)D * D / 8;
        int blks = (int)(n8 / 256);
        conv_triple_kernel<<<blks, 256>>>(wq, wq3, n8, 1);
        conv_triple_kernel<<<blks, 256>>>(wk, wk3, n8, 1);
        conv_triple_kernel<<<blks, 256>>>(wv, wv3, n8, 1);
        conv_triple_kernel<<<blks, 256>>>(wo, wo3, n8, 1);
        size_t n8f = (size_t)D_FF * D / 8;
        int blksf = (int)(n8f / 256);
        conv_triple_kernel<<<blksf, 256>>>(wup, wup3, n8f, 1);
        conv_triple_kernel<<<blksf, 256>>>(wdn, wdn3, n8f, 1);
    }

    // 1) h3 = triple(rmsnorm(x, n1w))
    rmsnorm_triple_kernel<<<U, 256>>>(x, n1w, h3);

    // 2-4) q3 (triple-A), k3 (triple-B), v (fp32)  — big-GEMM kernel
    dim3 gDD(D / TCG_TN, U / 128, 1);
    tcg_gemm_kernel<<<gDD, 256, TCG_SMEM>>>(h3, K3D, wq3, K3D,
                                            nullptr, q3, D, K3D,
                                            nullptr, nullptr, 0, 0, 1);
    tcg_gemm_kernel<<<gDD, 256, TCG_SMEM>>>(h3, K3D, wk3, K3D,
                                            nullptr, k3, D, K3D,
                                            nullptr, nullptr, 0, 0, 2);
    tcg_gemm_kernel<<<gDD, 256, TCG_SMEM>>>(h3, K3D, wv3, K3D,
                                            v, nullptr, D, K3D,
                                            nullptr, nullptr, 0, 0, 0);

    // v -> vT3 (B-style, transposed)
    vtrans_kernel<<<dim3(D / 32, U / 64), 256>>>(v, vT3);

    // 5) scores[z] = q_z k_z^T * scale + adj  (fp32) — mma.sync
    dim3 gS(U / GBN, U / GBM, N_HEADS);
    gemm_bf16_kernel<<<gS, 256>>>(q3, K3D, (size_t)K3H,
                                  k3, K3D, (size_t)K3H,
                                  sc, nullptr, U, (size_t)U * U, 0, K3H,
                                  nullptr, adj, U, nullptr, 0, attn_scale, 0, 0);

    // 6) softmax rows -> attn3 (triple-A)
    softmax_triple_kernel<<<N_HEADS * U, 256>>>(sc, attn3);

    // 7) ao3 (reuse h3) = attn3 @ vT3^T  — mma.sync (N=128 per head)
    dim3 gPV(D_HEAD / GBN, U / GBM, N_HEADS);
    gemm_bf16_kernel<<<gPV, 256>>>(attn3, K3U, (size_t)U * K3U,
                                   vT3, K3U, (size_t)D_HEAD * K3U,
                                   nullptr, h3, D, 0, D_HEAD, K3U,
                                   nullptr, nullptr, 0, nullptr, 0, 1.0f, 0, 1);

    // 8) x2 = x + ao @ wo^T (fp32)
    tcg_gemm_kernel<<<gDD, 256, TCG_SMEM>>>(h3, K3D, wo3, K3D,
                                            x2, nullptr, D, K3D,
                                            nullptr, x, D, 0, 0);

    // 9) h3 = triple(rmsnorm(x2, n2w))
    rmsnorm_triple_kernel<<<U, 256>>>(x2, n2w, h3);

    // 10) ff3 = triple-A(gelu(h2 @ wup^T + bup))
    dim3 gUP(D_FF / TCG_TN, U / 128, 1);
    tcg_gemm_kernel<<<gUP, 256, TCG_SMEM>>>(h3, K3D, wup3, K3D,
                                            nullptr, ff3, D_FF, K3D,
                                            bup, nullptr, 0, 1, 1);

    // 11) out = x2 + ff @ wdn^T + bdn (fp32)
    dim3 gDN(D / TCG_TN, U / 128, 1);
    tcg_gemm_kernel<<<gDN, 256, TCG_SMEM>>>(ff3, K3F, wdn3, K3F,
                                            out, nullptr, D, K3F,
                                            bdn, x2, D, 0, 0);
}

// round 6
// speedup vs baseline: 4.2570x; 2.1353x over previous
#include <cuda_runtime.h>
#include <cuda_bf16.h>
#include <math.h>
#include <stdint.h>

#define U 2048
#define D 2048
#define N_HEADS 16
#define D_HEAD 128
#define D_FF 8192
#define EPS 1e-6f

#define K3D (3*D)       // 6144
#define K3H (3*D_HEAD)  // 384
#define K3F (3*D_FF)    // 24576
#define K3U (3*U)       // 6144

// tcgen05 availability: only on arch-specific ('a') targets.
#if !defined(__CUDA_ARCH__) || defined(__CUDA_ARCH_FEAT_SM103_ALL) || defined(__CUDA_ARCH_FEAT_SM100_ALL) || defined(__CUDA_ARCH_FEAT_SM101_ALL) || defined(__CUDA_ARCH_FEAT_SM110_ALL)
#define HAS_TCG 1
#else
#define HAS_TCG 0
#endif

// ---------------- scratch (device globals: allocation-free) ----------------
__device__ float g_scores[(size_t)N_HEADS * U * U];
__device__ float g_x2[(size_t)U * D];
__device__ float g_v[(size_t)U * D];
__device__ __nv_bfloat16 g_h3 [(size_t)U * K3D];
__device__ __nv_bfloat16 g_q3 [(size_t)U * K3D];
__device__ __nv_bfloat16 g_k3 [(size_t)U * K3D];
__device__ __nv_bfloat16 g_vT3[(size_t)D * K3U];
__device__ __nv_bfloat16 g_attn3[(size_t)N_HEADS * U * K3U];
__device__ __nv_bfloat16 g_ff3[(size_t)U * K3F];
__device__ __nv_bfloat16 g_wq3[(size_t)D * K3D];
__device__ __nv_bfloat16 g_wk3[(size_t)D * K3D];
__device__ __nv_bfloat16 g_wv3[(size_t)D * K3D];
__device__ __nv_bfloat16 g_wo3[(size_t)D * K3D];
__device__ __nv_bfloat16 g_wup3[(size_t)D_FF * K3D];
__device__ __nv_bfloat16 g_wdn3[(size_t)D * K3F];

// ---------------- packing helpers ----------------
__device__ __forceinline__ void split2(float x, __nv_bfloat16& hi, __nv_bfloat16& lo) {
    hi = __float2bfloat16(x);
    lo = __float2bfloat16(x - __bfloat162float(hi));
}
__device__ __forceinline__ uint32_t pk(__nv_bfloat16 a, __nv_bfloat16 b) {
    return (uint32_t)__bfloat16_as_ushort(a) | ((uint32_t)__bfloat16_as_ushort(b) << 16);
}
// A-style: per pair (x0,x1) emit words (h0,l0)(h0,h1)(l1,h1)
__device__ __forceinline__ void trip_a_w(uint32_t* w, float x0, float x1) {
    __nv_bfloat16 h0, l0, h1, l1; split2(x0, h0, l0); split2(x1, h1, l1);
    w[0] = pk(h0, l0); w[1] = pk(h0, h1); w[2] = pk(l1, h1);
}
// B-style: (h0,h0)(l0,h1)(h1,l1)
__device__ __forceinline__ void trip_b_w(uint32_t* w, float x0, float x1) {
    __nv_bfloat16 h0, l0, h1, l1; split2(x0, h0, l0); split2(x1, h1, l1);
    w[0] = pk(h0, h0); w[1] = pk(l0, h1); w[2] = pk(h1, l1);
}
// 8 floats -> 12 words -> 3 uint4 stores at dst (16B aligned)
__device__ __forceinline__ void trip8_store(uint4* dst, const float* xs, int styleB) {
    uint32_t w[12];
    if (styleB) {
        #pragma unroll
        for (int m = 0; m < 4; m++) trip_b_w(w + 3 * m, xs[2 * m], xs[2 * m + 1]);
    } else {
        #pragma unroll
        for (int m = 0; m < 4; m++) trip_a_w(w + 3 * m, xs[2 * m], xs[2 * m + 1]);
    }
    const uint4* v = (const uint4*)w;
    dst[0] = v[0]; dst[1] = v[1]; dst[2] = v[2];
}

__device__ __forceinline__ void cp16(void* smem, const void* gmem) {
    uint32_t s = (uint32_t)__cvta_generic_to_shared(smem);
    asm volatile("cp.async.ca.shared.global [%0], [%1], 16;\n" :: "r"(s), "l"(gmem));
}
__device__ __forceinline__ void cpcommit() { asm volatile("cp.async.commit_group;\n"); }
__device__ __forceinline__ void cpwait0() { asm volatile("cp.async.wait_group 0;\n"); }
__device__ __forceinline__ void cpwait1() { asm volatile("cp.async.wait_group 1;\n"); }

#if !HAS_TCG
__device__ __forceinline__ void mma16816(float* c, const uint32_t* a, const uint32_t* b) {
    asm volatile(
        "mma.sync.aligned.m16n8k16.row.col.f32.bf16.bf16.f32 "
        "{%0,%1,%2,%3}, {%4,%5,%6,%7}, {%8,%9}, {%0,%1,%2,%3};\n"
        : "+f"(c[0]), "+f"(c[1]), "+f"(c[2]), "+f"(c[3])
        : "r"(a[0]), "r"(a[1]), "r"(a[2]), "r"(a[3]), "r"(b[0]), "r"(b[1]));
}
#endif

#if HAS_TCG
// ---------------- tcgen05 helpers ----------------
__device__ __forceinline__ uint32_t elect_one_pred() {
    uint32_t pred;
    asm volatile(
        "{\n\t.reg .pred p;\n\telect.sync _|p, 0xFFFFFFFF;\n\tselp.b32 %0, 1, 0, p;\n\t}"
        : "=r"(pred));
    return pred;
}
#define TCG_ALLOC(dst, n)  asm volatile("tcgen05.alloc.cta_group::1.sync.aligned.shared::cta.b32 [%0], %1;" :: "r"(dst), "r"(n) : "memory")
#define TCG_DEALLOC(t, n)  asm volatile("tcgen05.dealloc.cta_group::1.sync.aligned.b32 %0, %1;" :: "r"(t), "r"(n))
#define TCG_COMMIT(mb)     asm volatile("tcgen05.commit.cta_group::1.mbarrier::arrive::one.shared::cluster.b64 [%0];" :: "r"(mb) : "memory")
#define TCG_FENCE_AFTER()  asm volatile("tcgen05.fence::after_thread_sync;" ::: "memory")
#define TCG_FENCE_BEFORE() asm volatile("tcgen05.fence::before_thread_sync;" ::: "memory")
#define TCG_WAIT_LD()      asm volatile("tcgen05.wait::ld.sync.aligned;" ::: "memory")
#define FENCE_ASYNC_SHARED() asm volatile("fence.proxy.async.shared::cta;" ::: "memory")
#define MBAR_INIT(mb, c)   asm volatile("mbarrier.init.shared.b64 [%0], %1;" :: "r"(mb), "r"(c) : "memory")

__device__ __forceinline__ void mbar_wait_parity(uint32_t mbar, uint32_t parity) {
    uint32_t done;
    asm volatile(
        "{\n\t.reg .pred p;\n\t"
        "mbarrier.try_wait.parity.acquire.cta.shared::cta.b64 p, [%1], %2;\n\t"
        "selp.b32 %0, 1, 0, p;\n\t}"
        : "=r"(done) : "r"(mbar), "r"(parity) : "memory");
    if (!done) {
        asm volatile(
            "{\n\t.reg .pred P1;\n\t"
            "WAIT_LOOP_%=:\n\t"
            "mbarrier.try_wait.parity.acquire.cta.shared::cta.b64 P1, [%0], %1, 0x989680;\n\t"
            "@P1 bra.uni WAIT_DONE_%=;\n\t"
            "bra.uni WAIT_LOOP_%=;\n\t"
            "WAIT_DONE_%=:\n\t}"
            :: "r"(mbar), "r"(parity) : "memory");
    }
}

__device__ __forceinline__ void tcg_ld_x32(uint32_t* r, uint32_t taddr) {
    asm volatile(
        "tcgen05.ld.sync.aligned.32x32b.x32.b32 "
        "{%0,%1,%2,%3,%4,%5,%6,%7,%8,%9,%10,%11,%12,%13,%14,%15,"
        "%16,%17,%18,%19,%20,%21,%22,%23,%24,%25,%26,%27,%28,%29,%30,%31}, [%32];"
        : "=r"(r[0]), "=r"(r[1]), "=r"(r[2]), "=r"(r[3]), "=r"(r[4]), "=r"(r[5]),
          "=r"(r[6]), "=r"(r[7]), "=r"(r[8]), "=r"(r[9]), "=r"(r[10]), "=r"(r[11]),
          "=r"(r[12]), "=r"(r[13]), "=r"(r[14]), "=r"(r[15]), "=r"(r[16]), "=r"(r[17]),
          "=r"(r[18]), "=r"(r[19]), "=r"(r[20]), "=r"(r[21]), "=r"(r[22]), "=r"(r[23]),
          "=r"(r[24]), "=r"(r[25]), "=r"(r[26]), "=r"(r[27]), "=r"(r[28]), "=r"(r[29]),
          "=r"(r[30]), "=r"(r[31])
        : "r"(taddr));
}

__device__ __forceinline__ void tcg_mma_f16_ss(uint32_t d, uint64_t ad, uint64_t bd,
                                               uint32_t idesc, uint32_t en) {
    asm volatile(
        "{\n\t.reg .pred p;\n\tsetp.ne.u32 p, %5, 0;\n\t"
        "tcgen05.mma.cta_group::1.kind::f16 [%0], %1, %2, %3, {%4,%4,%4,%4}, p;\n\t}"
        :: "r"(d), "l"(ad), "l"(bd), "r"(idesc), "r"(0u), "r"(en) : "memory");
}

#define SMEM_DESC_BASE ( (uint64_t(2) << 61) | (uint64_t(1) << 46) \
                       | (uint64_t(64) << 32) | (uint64_t(1) << 16) )
#define MK_DESC(addr) (SMEM_DESC_BASE | ((uint64_t)((addr) >> 4) & 0x3FFF))
#endif // HAS_TCG

#define SWZ(o) ((o) ^ (((o) >> 3) & 0x70))

// ================= tcgen05 GEMM (templated tile-N) =========================
// C[m,n] = (sum_k A[m,k]*B[n,k]) * scale + bias + bias2d [+gelu] [+residual]
// Batched over blockIdx.z via element strides sA/sB/sC; triple output gets
// column offset z*czcol. out_mode: 0 fp32, 1 triple-A, 2 triple-B.
#define TCG_SMEM_SZ(TN) (1024 + 3 * 16384 + 3 * ((TN) * 128))

extern __shared__ char tcg_smem[];

template<int TN>
__global__ __launch_bounds__(256)
void tcg_gemm_kernel(const __nv_bfloat16* __restrict__ A, int lda, size_t sA,
                     const __nv_bfloat16* __restrict__ B, int ldb, size_t sB,
                     float* __restrict__ Cf, __nv_bfloat16* __restrict__ C3,
                     int ldc, size_t sC, int czcol,
                     int K,
                     const float* __restrict__ bias,
                     const float* __restrict__ bias2d, int ld2,
                     const float* __restrict__ residual, int ldr,
                     float scale, int do_gelu, int out_mode) {
    constexpr uint32_t IDESC = (1u << 4) | (1u << 7) | (1u << 10)
                             | ((TN / 8) << 17) | (8u << 24);
    constexpr int ST_B = TN * 128;
    const int z = blockIdx.z;
    A += (size_t)z * sA;
    B += (size_t)z * sB;
    if (Cf) Cf += (size_t)z * sC;
    const int colz = z * czcol;

    const int tid = threadIdx.x;
    const int wid = tid >> 5, lane = tid & 31;
    const int bm = blockIdx.y * 128;
    const int bn = blockIdx.x * TN;

#if HAS_TCG
    const uint32_t smem_base = (uint32_t)__cvta_generic_to_shared(tcg_smem);

    if (wid == 0) TCG_ALLOC(smem_base, TN);
    if (tid == 0) {
        MBAR_INIT(smem_base + 8,  1);
        MBAR_INIT(smem_base + 16, 1);
        MBAR_INIT(smem_base + 24, 1);
    }
    __syncthreads();
    uint32_t tmem_base;
    asm volatile("ld.shared.b32 %0, [%1];" : "=r"(tmem_base) : "r"(smem_base));

    auto load_stage = [&](int s, int k0) {
        char* sa = tcg_smem + 1024 + s * 16384;
        char* sb = tcg_smem + 1024 + 3 * 16384 + s * ST_B;
        #pragma unroll
        for (int i = 0; i < 4; i++) {
            int c = i * 256 + tid;
            int row = c >> 3, sub = c & 7;
            cp16(sa + SWZ(row * 128 + sub * 16),
                 A + (size_t)(bm + row) * lda + k0 + sub * 8);
        }
        #pragma unroll
        for (int i = 0; i < TN / 32; i++) {
            int c = i * 256 + tid;
            int row = c >> 3, sub = c & 7;
            cp16(sb + SWZ(row * 128 + sub * 16),
                 B + (size_t)(bn + row) * ldb + k0 + sub * 8);
        }
    };

    const int nIter = K / 64;

    load_stage(0, 0);  cpcommit();
    load_stage(1, 64); cpcommit();

    for (int it = 0; it < nIter; it++) {
        const int s = it % 3;
        if (it + 1 < nIter) cpwait1(); else cpwait0();
        __syncthreads();

        if (wid == 0) {
            if (elect_one_pred()) {
                FENCE_ASYNC_SHARED();
                uint64_t ad = MK_DESC(smem_base + 1024 + s * 16384);
                uint64_t bd = MK_DESC(smem_base + 1024 + 3 * 16384 + s * ST_B);
                #pragma unroll
                for (int ks = 0; ks < 4; ks++)
                    tcg_mma_f16_ss(tmem_base, ad + ks * 2, bd + ks * 2,
                                   IDESC, (it > 0 || ks > 0) ? 1u : 0u);
                TCG_COMMIT(smem_base + 8 + s * 8);
            }
        }

        if (it + 2 < nIter) {
            const int sl = (it + 2) % 3;
            if (it + 2 >= 3) {
                const int n = (it + 2) / 3;
                mbar_wait_parity(smem_base + 8 + sl * 8, (uint32_t)((n - 1) & 1));
            }
            load_stage(sl, (it + 2) * 64);
            cpcommit();
        }
    }

    {
        const int sl = (nIter - 1) % 3;
        const int n = (nIter - 1) / 3 + 1;
        mbar_wait_parity(smem_base + 8 + sl * 8, (uint32_t)((n - 1) & 1));
    }
    TCG_FENCE_AFTER();

    // epilogue: 8 warps = 4 row groups x 2 col halves
    const int row = bm + (wid & 3) * 32 + lane;
    const int colbase = (wid >> 2) * (TN / 2);
    #pragma unroll
    for (int ch = 0; ch < TN / 64; ch++) {
        const int c0 = colbase + ch * 32;
        uint32_t r[32];
        tcg_ld_x32(r, tmem_base + c0);
        TCG_WAIT_LD();
        float vals[32];
        #pragma unroll
        for (int j = 0; j < 32; j++) {
            const int col = bn + c0 + j;
            float v = __uint_as_float(r[j]) * scale;
            if (bias)   v += bias[col];
            if (bias2d) v += bias2d[(size_t)row * ld2 + col];
            if (do_gelu) v = 0.5f * v * (1.0f + erff(v * 0.70710678118654752f));
            if (residual) v += residual[(size_t)row * ldr + col];
            vals[j] = v;
        }
        if (out_mode == 0) {
            float4* dst = (float4*)(Cf + (size_t)row * ldc + bn + c0);
            const float4* src = (const float4*)vals;
            #pragma unroll
            for (int q = 0; q < 8; q++) dst[q] = src[q];
        } else {
            uint32_t w[48];
            #pragma unroll
            for (int p = 0; p < 16; p++) {
                if (out_mode == 1) trip_a_w(w + 3 * p, vals[2 * p], vals[2 * p + 1]);
                else               trip_b_w(w + 3 * p, vals[2 * p], vals[2 * p + 1]);
            }
            uint4* dst = (uint4*)(C3 + (size_t)row * (3 * (size_t)ldc)
                                  + 3 * (size_t)(bn + c0 + colz));
            const uint4* src = (const uint4*)w;
            #pragma unroll
            for (int q = 0; q < 12; q++) dst[q] = src[q];
        }
    }

    TCG_FENCE_BEFORE();
    __syncthreads();
    if (wid == 0) TCG_DEALLOC(tmem_base, TN);

#else  // ---------------- mma.sync fallback (non-'a' PTX stage) -------------
    constexpr int ASTR = 40;
    __nv_bfloat16* As = (__nv_bfloat16*)tcg_smem;
    __nv_bfloat16* Bs = As + 2 * 128 * ASTR;
    const int wm = wid >> 2, wn = wid & 3;
    const int g = lane >> 2, t4 = lane & 3;

    for (int halfn = 0; halfn < TN / 128; halfn++) {
        const int bn2 = bn + halfn * 128;
        float acc[4][4][4];
        #pragma unroll
        for (int i = 0; i < 4; i++)
            #pragma unroll
            for (int j = 0; j < 4; j++)
                #pragma unroll
                for (int c = 0; c < 4; c++) acc[i][j][c] = 0.f;

        auto loadTiles = [&](int k0, int buf) {
            #pragma unroll
            for (int it2 = 0; it2 < 2; it2++) {
                int e = tid + it2 * 256;
                int rw = e >> 2, c = e & 3;
                cp16(&As[buf * 128 * ASTR + rw * ASTR + c * 8],
                     A + (size_t)(bm + rw) * lda + k0 + c * 8);
                cp16(&Bs[buf * 128 * ASTR + rw * ASTR + c * 8],
                     B + (size_t)(bn2 + rw) * ldb + k0 + c * 8);
            }
        };

        const int nIter = K / 32;
        loadTiles(0, 0);
        cpcommit();
        for (int it = 0; it < nIter; it++) {
            const int buf = it & 1;
            if (it + 1 < nIter) { loadTiles((it + 1) * 32, buf ^ 1); cpcommit(); cpwait1(); }
            else cpwait0();
            __syncthreads();
            #pragma unroll
            for (int ks = 0; ks < 2; ks++) {
                const int kb = ks * 16;
                uint32_t afr[4][4], bfr[4][2];
                #pragma unroll
                for (int mi = 0; mi < 4; mi++) {
                    const __nv_bfloat16* ab = &As[buf * 128 * ASTR + (wm * 64 + mi * 16 + g) * ASTR + kb + 2 * t4];
                    afr[mi][0] = *(const uint32_t*)ab;
                    afr[mi][1] = *(const uint32_t*)(ab + 8 * ASTR);
                    afr[mi][2] = *(const uint32_t*)(ab + 8);
                    afr[mi][3] = *(const uint32_t*)(ab + 8 * ASTR + 8);
                }
                #pragma unroll
                for (int nj = 0; nj < 4; nj++) {
                    const __nv_bfloat16* bb = &Bs[buf * 128 * ASTR + (wn * 32 + nj * 8 + g) * ASTR + kb + 2 * t4];
                    bfr[nj][0] = *(const uint32_t*)bb;
                    bfr[nj][1] = *(const uint32_t*)(bb + 8);
                }
                #pragma unroll
                for (int mi = 0; mi < 4; mi++)
                    #pragma unroll
                    for (int nj = 0; nj < 4; nj++)
                        mma16816(acc[mi][nj], afr[mi], bfr[nj]);
            }
            __syncthreads();
        }

        #pragma unroll
        for (int mi = 0; mi < 4; mi++)
            #pragma unroll
            for (int nj = 0; nj < 4; nj++)
                #pragma unroll
                for (int half = 0; half < 2; half++) {
                    const int row = bm + wm * 64 + mi * 16 + g + half * 8;
                    const int col = bn2 + wn * 32 + nj * 8 + 2 * t4;
                    float v0 = acc[mi][nj][half * 2 + 0] * scale;
                    float v1 = acc[mi][nj][half * 2 + 1] * scale;
                    if (bias)   { v0 += bias[col]; v1 += bias[col + 1]; }
                    if (bias2d) { v0 += bias2d[(size_t)row * ld2 + col];
                                  v1 += bias2d[(size_t)row * ld2 + col + 1]; }
                    if (do_gelu) {
                        v0 = 0.5f * v0 * (1.0f + erff(v0 * 0.70710678118654752f));
                        v1 = 0.5f * v1 * (1.0f + erff(v1 * 0.70710678118654752f));
                    }
                    if (residual) { v0 += residual[(size_t)row * ldr + col];
                                    v1 += residual[(size_t)row * ldr + col + 1]; }
                    if (out_mode == 0) {
                        float2 w2; w2.x = v0; w2.y = v1;
                        *(float2*)(Cf + (size_t)row * ldc + col) = w2;
                    } else {
                        uint32_t w[3];
                        if (out_mode == 1) trip_a_w(w, v0, v1);
                        else               trip_b_w(w, v0, v1);
                        uint32_t* p = (uint32_t*)(C3 + (size_t)row * (3 * (size_t)ldc) + 3 * (size_t)(col + colz));
                        // 3*(col) may be odd-word aligned only to 4B for 2-col writes; store words
                        p[0] = w[0]; p[1] = w[1]; p[2] = w[2];
                    }
                }
        __syncthreads();
    }
#endif
}

// ---------------- triple conversion (fp32 [R,C] -> bf16 [R,3C]) ------------
__global__ void conv_triple_kernel(const float* __restrict__ in,
                                   __nv_bfloat16* __restrict__ out,
                                   size_t n8, int styleB) {
    size_t g = (size_t)blockIdx.x * 256 + threadIdx.x;
    if (g >= n8) return;
    const float4* p = (const float4*)(in + g * 8);
    float4 a = p[0], b = p[1];
    float xs[8] = {a.x, a.y, a.z, a.w, b.x, b.y, b.z, b.w};
    trip8_store((uint4*)(out + g * 24), xs, styleB);
}

// ---------------- RMSNorm -> A-style triple ----------------
__global__ void rmsnorm_triple_kernel(const float* __restrict__ x,
                                      const float* __restrict__ w,
                                      __nv_bfloat16* __restrict__ out) {
    const int row = blockIdx.x;
    const int tid = threadIdx.x;
    __shared__ float red[8];
    const float4* xr = (const float4*)(x + (size_t)row * D + tid * 8);
    const float4* wr = (const float4*)(w + tid * 8);
    float4 xa = xr[0], xb = xr[1];
    float4 wa = wr[0], wb = wr[1];
    float xs[8] = {xa.x, xa.y, xa.z, xa.w, xb.x, xb.y, xb.z, xb.w};
    float ws[8] = {wa.x, wa.y, wa.z, wa.w, wb.x, wb.y, wb.z, wb.w};
    float ss = 0.f;
    #pragma unroll
    for (int i = 0; i < 8; i++) ss += xs[i] * xs[i];
    #pragma unroll
    for (int o = 16; o; o >>= 1) ss += __shfl_xor_sync(0xffffffffu, ss, o);
    if ((tid & 31) == 0) red[tid >> 5] = ss;
    __syncthreads();
    float tot = 0.f;
    #pragma unroll
    for (int i = 0; i < 8; i++) tot += red[i];
    const float r = rsqrtf(tot / (float)D + EPS);
    #pragma unroll
    for (int i = 0; i < 8; i++) xs[i] = xs[i] * r * ws[i];
    trip8_store((uint4*)(out + (size_t)row * K3D + tid * 24), xs, 0);
}

// ---------------- softmax fp32 row -> A-style triple row ----------------
__global__ void softmax_triple_kernel(const float* __restrict__ s,
                                      __nv_bfloat16* __restrict__ out) {
    const size_t row = blockIdx.x;
    const int tid = threadIdx.x;
    __shared__ float red[8];
    const float4* p = (const float4*)(s + row * U + tid * 8);
    float4 a = p[0], b = p[1];
    float xs[8] = {a.x, a.y, a.z, a.w, b.x, b.y, b.z, b.w};

    float m = -1e30f;
    #pragma unroll
    for (int i = 0; i < 8; i++) m = fmaxf(m, xs[i]);
    #pragma unroll
    for (int o = 16; o; o >>= 1) m = fmaxf(m, __shfl_xor_sync(0xffffffffu, m, o));
    if ((tid & 31) == 0) red[tid >> 5] = m;
    __syncthreads();
    #pragma unroll
    for (int i = 0; i < 8; i++) m = fmaxf(m, red[i]);
    __syncthreads();

    float sum = 0.f;
    #pragma unroll
    for (int i = 0; i < 8; i++) { xs[i] = __expf(xs[i] - m); sum += xs[i]; }
    #pragma unroll
    for (int o = 16; o; o >>= 1) sum += __shfl_xor_sync(0xffffffffu, sum, o);
    if ((tid & 31) == 0) red[tid >> 5] = sum;
    __syncthreads();
    float tot = 0.f;
    #pragma unroll
    for (int i = 0; i < 8; i++) tot += red[i];
    const float inv = 1.0f / tot;
    #pragma unroll
    for (int i = 0; i < 8; i++) xs[i] *= inv;
    trip8_store((uint4*)(out + row * (size_t)K3U + tid * 24), xs, 0);
}

// ---------------- v [U,D] -> vT3 [D][3U] B-style transpose ----------------
__global__ void vtrans_kernel(const float* __restrict__ v,
                              __nv_bfloat16* __restrict__ out) {
    const int tx = threadIdx.x & 31, ty = threadIdx.x >> 5;
    const int col = blockIdx.x * 32 + tx;
    const int k0 = blockIdx.y * 64 + ty * 8;
    float xs[8];
    #pragma unroll
    for (int i = 0; i < 8; i++) xs[i] = v[(size_t)(k0 + i) * D + col];
    trip8_store((uint4*)(out + (size_t)col * K3U + (size_t)k0 * 3), xs, 1);
}

// ---------------- launch ----------------
extern "C" void kernel_launch(void* const* d_in, const int* in_sizes, int n_in,
                              void* d_out, int out_size) {
    const float* x   = (const float*)d_in[0];
    const float* adj = (const float*)d_in[1];
    const float* n1w = (const float*)d_in[2];
    const float* n2w = (const float*)d_in[3];
    const float* wq  = (const float*)d_in[4];
    const float* wk  = (const float*)d_in[5];
    const float* wv  = (const float*)d_in[6];
    const float* wo  = (const float*)d_in[7];
    const float* wup = (const float*)d_in[8];
    const float* bup = (const float*)d_in[9];
    const float* wdn = (const float*)d_in[10];
    const float* bdn = (const float*)d_in[11];
    float* out = (float*)d_out;

    static float *sc = nullptr, *x2, *v;
    static __nv_bfloat16 *h3, *q3, *k3, *vT3, *attn3, *ff3,
                         *wq3, *wk3, *wv3, *wo3, *wup3, *wdn3;
    static bool attr_done = false;
    if (!sc) {
        cudaGetSymbolAddress((void**)&sc, g_scores);
        cudaGetSymbolAddress((void**)&x2, g_x2);
        cudaGetSymbolAddress((void**)&v,  g_v);
        cudaGetSymbolAddress((void**)&h3, g_h3);
        cudaGetSymbolAddress((void**)&q3, g_q3);
        cudaGetSymbolAddress((void**)&k3, g_k3);
        cudaGetSymbolAddress((void**)&vT3, g_vT3);
        cudaGetSymbolAddress((void**)&attn3, g_attn3);
        cudaGetSymbolAddress((void**)&ff3, g_ff3);
        cudaGetSymbolAddress((void**)&wq3, g_wq3);
        cudaGetSymbolAddress((void**)&wk3, g_wk3);
        cudaGetSymbolAddress((void**)&wv3, g_wv3);
        cudaGetSymbolAddress((void**)&wo3, g_wo3);
        cudaGetSymbolAddress((void**)&wup3, g_wup3);
        cudaGetSymbolAddress((void**)&wdn3, g_wdn3);
    }
    if (!attr_done) {
        cudaFuncSetAttribute(tcg_gemm_kernel<256>,
                             cudaFuncAttributeMaxDynamicSharedMemorySize, TCG_SMEM_SZ(256));
        cudaFuncSetAttribute(tcg_gemm_kernel<128>,
                             cudaFuncAttributeMaxDynamicSharedMemorySize, TCG_SMEM_SZ(128));
        attr_done = true;
    }

    const float attn_scale = 0.08838834764831845f; // 1/sqrt(128)

    // --- weight conversions (B-style triples) ---
    {
        size_t n8 = (size_t)D * D / 8;
        int blks = (int)(n8 / 256);
        conv_triple_kernel<<<blks, 256>>>(wq, wq3, n8, 1);
        conv_triple_kernel<<<blks, 256>>>(wk, wk3, n8, 1);
        conv_triple_kernel<<<blks, 256>>>(wv, wv3, n8, 1);
        conv_triple_kernel<<<blks, 256>>>(wo, wo3, n8, 1);
        size_t n8f = (size_t)D_FF * D / 8;
        int blksf = (int)(n8f / 256);
        conv_triple_kernel<<<blksf, 256>>>(wup, wup3, n8f, 1);
        conv_triple_kernel<<<blksf, 256>>>(wdn, wdn3, n8f, 1);
    }

    // 1) h3 = triple(rmsnorm(x, n1w))
    rmsnorm_triple_kernel<<<U, 256>>>(x, n1w, h3);

    // 2-4) q3 (triple-A), k3 (triple-B), v (fp32)
    dim3 gDD(D / 256, U / 128, 1);
    tcg_gemm_kernel<256><<<gDD, 256, TCG_SMEM_SZ(256)>>>(
        h3, K3D, 0, wq3, K3D, 0, nullptr, q3, D, 0, 0, K3D,
        nullptr, nullptr, 0, nullptr, 0, 1.0f, 0, 1);
    tcg_gemm_kernel<256><<<gDD, 256, TCG_SMEM_SZ(256)>>>(
        h3, K3D, 0, wk3, K3D, 0, nullptr, k3, D, 0, 0, K3D,
        nullptr, nullptr, 0, nullptr, 0, 1.0f, 0, 2);
    tcg_gemm_kernel<256><<<gDD, 256, TCG_SMEM_SZ(256)>>>(
        h3, K3D, 0, wv3, K3D, 0, v, nullptr, D, 0, 0, K3D,
        nullptr, nullptr, 0, nullptr, 0, 1.0f, 0, 0);

    // v -> vT3 (B-style, transposed)
    vtrans_kernel<<<dim3(D / 32, U / 64), 256>>>(v, vT3);

    // 5) scores[z] = q_z k_z^T * scale + adj  (fp32) — tcgen05, batched
    dim3 gS(U / 256, U / 128, N_HEADS);
    tcg_gemm_kernel<256><<<gS, 256, TCG_SMEM_SZ(256)>>>(
        q3, K3D, (size_t)K3H, k3, K3D, (size_t)K3H,
        sc, nullptr, U, (size_t)U * U, 0, K3H,
        nullptr, adj, U, nullptr, 0, attn_scale, 0, 0);

    // 6) softmax rows -> attn3 (triple-A)
    softmax_triple_kernel<<<N_HEADS * U, 256>>>(sc, attn3);

    // 7) ao3 (reuse h3) = attn3 @ vT3^T — tcgen05 N=128, batched per head
    dim3 gPV(1, U / 128, N_HEADS);
    tcg_gemm_kernel<128><<<gPV, 256, TCG_SMEM_SZ(128)>>>(
        attn3, K3U, (size_t)U * K3U, vT3, K3U, (size_t)D_HEAD * K3U,
        nullptr, h3, D, 0, D_HEAD, K3U,
        nullptr, nullptr, 0, nullptr, 0, 1.0f, 0, 1);

    // 8) x2 = x + ao @ wo^T (fp32)
    tcg_gemm_kernel<256><<<gDD, 256, TCG_SMEM_SZ(256)>>>(
        h3, K3D, 0, wo3, K3D, 0, x2, nullptr, D, 0, 0, K3D,
        nullptr, nullptr, 0, x, D, 1.0f, 0, 0);

    // 9) h3 = triple(rmsnorm(x2, n2w))
    rmsnorm_triple_kernel<<<U, 256>>>(x2, n2w, h3);

    // 10) ff3 = triple-A(gelu(h2 @ wup^T + bup))
    dim3 gUP(D_FF / 256, U / 128, 1);
    tcg_gemm_kernel<256><<<gUP, 256, TCG_SMEM_SZ(256)>>>(
        h3, K3D, 0, wup3, K3D, 0, nullptr, ff3, D_FF, 0, 0, K3D,
        bup, nullptr, 0, nullptr, 0, 1.0f, 1, 1);

    // 11) out = x2 + ff @ wdn^T + bdn (fp32)
    dim3 gDN(D / 256, U / 128, 1);
    tcg_gemm_kernel<256><<<gDN, 256, TCG_SMEM_SZ(256)>>>(
        ff3, K3F, 0, wdn3, K3F, 0, out, nullptr, D, 0, 0, K3F,
        bdn, x2, D, 0, 0, 1.0f, 0, 0);
}

// round 7
// speedup vs baseline: 4.8377x; 1.1364x over previous
#include <cuda_runtime.h>
#include <cuda_bf16.h>
#include <math.h>
#include <stdint.h>

#define U 2048
#define D 2048
#define N_HEADS 16
#define D_HEAD 128
#define D_FF 8192
#define EPS 1e-6f

#define K3D (3*D)       // 6144
#define K3H (3*D_HEAD)  // 384
#define K3F (3*D_FF)    // 24576
#define K3U (3*U)       // 6144

#if !defined(__CUDA_ARCH__) || defined(__CUDA_ARCH_FEAT_SM103_ALL) || defined(__CUDA_ARCH_FEAT_SM100_ALL) || defined(__CUDA_ARCH_FEAT_SM101_ALL) || defined(__CUDA_ARCH_FEAT_SM110_ALL)
#define HAS_TCG 1
#else
#define HAS_TCG 0
#endif

// ---------------- scratch ----------------
__device__ float g_scores[(size_t)N_HEADS * U * U];   // also: K-split partial buffers
__device__ float g_x2[(size_t)U * D];
__device__ float g_v[(size_t)U * D];
__device__ __nv_bfloat16 g_h3 [(size_t)U * K3D];
__device__ __nv_bfloat16 g_q3 [(size_t)U * K3D];
__device__ __nv_bfloat16 g_k3 [(size_t)U * K3D];
__device__ __nv_bfloat16 g_vT3[(size_t)D * K3U];
__device__ __nv_bfloat16 g_attn3[(size_t)N_HEADS * U * K3U];
__device__ __nv_bfloat16 g_ff3[(size_t)U * K3F];
__device__ __nv_bfloat16 g_wqkv3[(size_t)3 * D * K3D];
__device__ __nv_bfloat16 g_wo3[(size_t)D * K3D];
__device__ __nv_bfloat16 g_wup3[(size_t)D_FF * K3D];
__device__ __nv_bfloat16 g_wdn3[(size_t)D * K3F];

// ---------------- packing helpers ----------------
__device__ __forceinline__ void split2(float x, __nv_bfloat16& hi, __nv_bfloat16& lo) {
    hi = __float2bfloat16(x);
    lo = __float2bfloat16(x - __bfloat162float(hi));
}
__device__ __forceinline__ uint32_t pk(__nv_bfloat16 a, __nv_bfloat16 b) {
    return (uint32_t)__bfloat16_as_ushort(a) | ((uint32_t)__bfloat16_as_ushort(b) << 16);
}
__device__ __forceinline__ void trip_a_w(uint32_t* w, float x0, float x1) {
    __nv_bfloat16 h0, l0, h1, l1; split2(x0, h0, l0); split2(x1, h1, l1);
    w[0] = pk(h0, l0); w[1] = pk(h0, h1); w[2] = pk(l1, h1);
}
__device__ __forceinline__ void trip_b_w(uint32_t* w, float x0, float x1) {
    __nv_bfloat16 h0, l0, h1, l1; split2(x0, h0, l0); split2(x1, h1, l1);
    w[0] = pk(h0, h0); w[1] = pk(l0, h1); w[2] = pk(h1, l1);
}
__device__ __forceinline__ void trip8_store(uint4* dst, const float* xs, int styleB) {
    uint32_t w[12];
    if (styleB) {
        #pragma unroll
        for (int m = 0; m < 4; m++) trip_b_w(w + 3 * m, xs[2 * m], xs[2 * m + 1]);
    } else {
        #pragma unroll
        for (int m = 0; m < 4; m++) trip_a_w(w + 3 * m, xs[2 * m], xs[2 * m + 1]);
    }
    const uint4* v = (const uint4*)w;
    dst[0] = v[0]; dst[1] = v[1]; dst[2] = v[2];
}

__device__ __forceinline__ void cp16(void* smem, const void* gmem) {
    uint32_t s = (uint32_t)__cvta_generic_to_shared(smem);
    asm volatile("cp.async.ca.shared.global [%0], [%1], 16;\n" :: "r"(s), "l"(gmem));
}
__device__ __forceinline__ void cpcommit() { asm volatile("cp.async.commit_group;\n"); }
__device__ __forceinline__ void cpwait0() { asm volatile("cp.async.wait_group 0;\n"); }
__device__ __forceinline__ void cpwait1() { asm volatile("cp.async.wait_group 1;\n"); }

#if HAS_TCG
__device__ __forceinline__ uint32_t elect_one_pred() {
    uint32_t pred;
    asm volatile(
        "{\n\t.reg .pred p;\n\telect.sync _|p, 0xFFFFFFFF;\n\tselp.b32 %0, 1, 0, p;\n\t}"
        : "=r"(pred));
    return pred;
}
#define TCG_ALLOC(dst, n)  asm volatile("tcgen05.alloc.cta_group::1.sync.aligned.shared::cta.b32 [%0], %1;" :: "r"(dst), "r"(n) : "memory")
#define TCG_DEALLOC(t, n)  asm volatile("tcgen05.dealloc.cta_group::1.sync.aligned.b32 %0, %1;" :: "r"(t), "r"(n))
#define TCG_COMMIT(mb)     asm volatile("tcgen05.commit.cta_group::1.mbarrier::arrive::one.shared::cluster.b64 [%0];" :: "r"(mb) : "memory")
#define TCG_FENCE_AFTER()  asm volatile("tcgen05.fence::after_thread_sync;" ::: "memory")
#define TCG_FENCE_BEFORE() asm volatile("tcgen05.fence::before_thread_sync;" ::: "memory")
#define TCG_WAIT_LD()      asm volatile("tcgen05.wait::ld.sync.aligned;" ::: "memory")
#define FENCE_ASYNC_SHARED() asm volatile("fence.proxy.async.shared::cta;" ::: "memory")
#define MBAR_INIT(mb, c)   asm volatile("mbarrier.init.shared.b64 [%0], %1;" :: "r"(mb), "r"(c) : "memory")

__device__ __forceinline__ void mbar_wait_parity(uint32_t mbar, uint32_t parity) {
    uint32_t done;
    asm volatile(
        "{\n\t.reg .pred p;\n\t"
        "mbarrier.try_wait.parity.acquire.cta.shared::cta.b64 p, [%1], %2;\n\t"
        "selp.b32 %0, 1, 0, p;\n\t}"
        : "=r"(done) : "r"(mbar), "r"(parity) : "memory");
    if (!done) {
        asm volatile(
            "{\n\t.reg .pred P1;\n\t"
            "WAIT_LOOP_%=:\n\t"
            "mbarrier.try_wait.parity.acquire.cta.shared::cta.b64 P1, [%0], %1, 0x989680;\n\t"
            "@P1 bra.uni WAIT_DONE_%=;\n\t"
            "bra.uni WAIT_LOOP_%=;\n\t"
            "WAIT_DONE_%=:\n\t}"
            :: "r"(mbar), "r"(parity) : "memory");
    }
}

__device__ __forceinline__ void tcg_ld_x32(uint32_t* r, uint32_t taddr) {
    asm volatile(
        "tcgen05.ld.sync.aligned.32x32b.x32.b32 "
        "{%0,%1,%2,%3,%4,%5,%6,%7,%8,%9,%10,%11,%12,%13,%14,%15,"
        "%16,%17,%18,%19,%20,%21,%22,%23,%24,%25,%26,%27,%28,%29,%30,%31}, [%32];"
        : "=r"(r[0]), "=r"(r[1]), "=r"(r[2]), "=r"(r[3]), "=r"(r[4]), "=r"(r[5]),
          "=r"(r[6]), "=r"(r[7]), "=r"(r[8]), "=r"(r[9]), "=r"(r[10]), "=r"(r[11]),
          "=r"(r[12]), "=r"(r[13]), "=r"(r[14]), "=r"(r[15]), "=r"(r[16]), "=r"(r[17]),
          "=r"(r[18]), "=r"(r[19]), "=r"(r[20]), "=r"(r[21]), "=r"(r[22]), "=r"(r[23]),
          "=r"(r[24]), "=r"(r[25]), "=r"(r[26]), "=r"(r[27]), "=r"(r[28]), "=r"(r[29]),
          "=r"(r[30]), "=r"(r[31])
        : "r"(taddr));
}

__device__ __forceinline__ void tcg_mma_f16_ss(uint32_t d, uint64_t ad, uint64_t bd,
                                               uint32_t idesc, uint32_t en) {
    asm volatile(
        "{\n\t.reg .pred p;\n\tsetp.ne.u32 p, %5, 0;\n\t"
        "tcgen05.mma.cta_group::1.kind::f16 [%0], %1, %2, %3, {%4,%4,%4,%4}, p;\n\t}"
        :: "r"(d), "l"(ad), "l"(bd), "r"(idesc), "r"(0u), "r"(en) : "memory");
}

#define SMEM_DESC_BASE ( (uint64_t(2) << 61) | (uint64_t(1) << 46) \
                       | (uint64_t(64) << 32) | (uint64_t(1) << 16) )
#define MK_DESC(addr) (SMEM_DESC_BASE | ((uint64_t)((addr) >> 4) & 0x3FFF))
#endif

#define SWZ(o) ((o) ^ (((o) >> 3) & 0x70))

// ============== tcgen05 GEMM: M=256 (dual-MMA) x TN, 3-stage pipeline ======
// out_mode: 0 fp32, 1 triple-A, 2 triple-B, 3 per-z QKV (z0:A->C3, z1:B->C3b, z2:fp32->Cf)
#define ST_A 32768
#define TCG_SMEM_SZ(TN) (1024 + 3 * ST_A + 3 * ((TN) * 128))

extern __shared__ char tcg_smem[];

template<int TN>
__global__ __launch_bounds__(256)
void tcg_gemm_kernel(const __nv_bfloat16* __restrict__ A, int lda, size_t sA,
                     const __nv_bfloat16* __restrict__ B, int ldb, size_t sB,
                     float* __restrict__ Cf, __nv_bfloat16* __restrict__ C3,
                     __nv_bfloat16* __restrict__ C3b,
                     int ldc, size_t sC, int czcol,
                     int K,
                     const float* __restrict__ bias,
                     const float* __restrict__ bias2d, int ld2,
                     const float* __restrict__ residual, int ldr,
                     float scale, int do_gelu, int out_mode) {
    constexpr uint32_t IDESC = (1u << 4) | (1u << 7) | (1u << 10)
                             | ((TN / 8) << 17) | (8u << 24);
    constexpr int ST_B = TN * 128;
    const int z = blockIdx.z;
    A += (size_t)z * sA;
    B += (size_t)z * sB;
    if (Cf) Cf += (size_t)z * sC;
    const int colz = z * czcol;

    const int tid = threadIdx.x;
    const int wid = tid >> 5, lane = tid & 31;
    const int bm = blockIdx.y * 256;
    const int bn = blockIdx.x * TN;

    int om = out_mode;
    __nv_bfloat16* C3o = C3;
    if (out_mode == 3) {
        if (z == 0) om = 1;
        else if (z == 1) { om = 2; C3o = C3b; }
        else om = 0;
    }

#if HAS_TCG
    const uint32_t smem_base = (uint32_t)__cvta_generic_to_shared(tcg_smem);

    if (wid == 0) TCG_ALLOC(smem_base, 512);
    if (tid == 0) {
        MBAR_INIT(smem_base + 8,  1);
        MBAR_INIT(smem_base + 16, 1);
        MBAR_INIT(smem_base + 24, 1);
    }
    __syncthreads();
    uint32_t tmem_base;
    asm volatile("ld.shared.b32 %0, [%1];" : "=r"(tmem_base) : "r"(smem_base));

    auto load_stage = [&](int s, int k0) {
        char* sa = tcg_smem + 1024 + s * ST_A;
        char* sb = tcg_smem + 1024 + 3 * ST_A + s * ST_B;
        #pragma unroll
        for (int i = 0; i < 8; i++) {           // A: 256 rows x 128B
            int c = i * 256 + tid;
            int row = c >> 3, sub = c & 7;
            cp16(sa + SWZ(row * 128 + sub * 16),
                 A + (size_t)(bm + row) * lda + k0 + sub * 8);
        }
        #pragma unroll
        for (int i = 0; i < TN / 32; i++) {     // B: TN rows x 128B
            int c = i * 256 + tid;
            int row = c >> 3, sub = c & 7;
            cp16(sb + SWZ(row * 128 + sub * 16),
                 B + (size_t)(bn + row) * ldb + k0 + sub * 8);
        }
    };

    const int nIter = K / 64;

    load_stage(0, 0);  cpcommit();
    load_stage(1, 64); cpcommit();

    for (int it = 0; it < nIter; it++) {
        const int s = it % 3;
        if (it + 1 < nIter) cpwait1(); else cpwait0();
        __syncthreads();

        if (wid == 0) {
            if (elect_one_pred()) {
                FENCE_ASYNC_SHARED();
                uint64_t ad = MK_DESC(smem_base + 1024 + s * ST_A);
                uint64_t bd = MK_DESC(smem_base + 1024 + 3 * ST_A + s * ST_B);
                #pragma unroll
                for (int ks = 0; ks < 4; ks++) {
                    uint32_t en = (it > 0 || ks > 0) ? 1u : 0u;
                    tcg_mma_f16_ss(tmem_base,       ad + ks * 2,        bd + ks * 2, IDESC, en);
                    tcg_mma_f16_ss(tmem_base + 256, ad + 1024 + ks * 2, bd + ks * 2, IDESC, en);
                }
                TCG_COMMIT(smem_base + 8 + s * 8);
            }
        }

        if (it + 2 < nIter) {
            const int sl = (it + 2) % 3;
            if (it + 2 >= 3) {
                const int n = (it + 2) / 3;
                mbar_wait_parity(smem_base + 8 + sl * 8, (uint32_t)((n - 1) & 1));
            }
            load_stage(sl, (it + 2) * 64);
            cpcommit();
        }
    }

    {
        const int sl = (nIter - 1) % 3;
        const int n = (nIter - 1) / 3 + 1;
        mbar_wait_parity(smem_base + 8 + sl * 8, (uint32_t)((n - 1) & 1));
    }
    TCG_FENCE_AFTER();

    // epilogue: warps 0-3 -> M-half 0 (cols 0..), warps 4-7 -> M-half 1 (cols 256..)
    const int h = wid >> 2;
    const int row = bm + h * 128 + (wid & 3) * 32 + lane;
    #pragma unroll
    for (int ch = 0; ch < TN / 32; ch++) {
        const int c0 = ch * 32;
        uint32_t r[32];
        tcg_ld_x32(r, tmem_base + h * 256 + c0);
        TCG_WAIT_LD();
        float vals[32];
        #pragma unroll
        for (int j = 0; j < 32; j++) {
            const int col = bn + c0 + j;
            float v = __uint_as_float(r[j]) * scale;
            if (bias)   v += bias[col];
            if (bias2d) v += bias2d[(size_t)row * ld2 + col];
            if (do_gelu) v = 0.5f * v * (1.0f + erff(v * 0.70710678118654752f));
            if (residual) v += residual[(size_t)row * ldr + col];
            vals[j] = v;
        }
        if (om == 0) {
            float4* dst = (float4*)(Cf + (size_t)row * ldc + bn + c0);
            const float4* src = (const float4*)vals;
            #pragma unroll
            for (int q = 0; q < 8; q++) dst[q] = src[q];
        } else {
            uint32_t w[48];
            #pragma unroll
            for (int p = 0; p < 16; p++) {
                if (om == 1) trip_a_w(w + 3 * p, vals[2 * p], vals[2 * p + 1]);
                else         trip_b_w(w + 3 * p, vals[2 * p], vals[2 * p + 1]);
            }
            uint4* dst = (uint4*)(C3o + (size_t)row * (3 * (size_t)ldc)
                                  + 3 * (size_t)(bn + c0 + colz));
            const uint4* src = (const uint4*)w;
            #pragma unroll
            for (int q = 0; q < 12; q++) dst[q] = src[q];
        }
    }

    TCG_FENCE_BEFORE();
    __syncthreads();
    if (wid == 0) TCG_DEALLOC(tmem_base, 512);

#else
    // naive (compile-only fallback for non-'a' PTX stage; never executed on sm_103a)
    for (int idx = tid; idx < 256 * (TN / 2); idx += 256) {
        const int mi = idx / (TN / 2);
        const int p2 = idx % (TN / 2);
        const int row = bm + mi;
        const int col = bn + 2 * p2;
        float a0 = 0.f, a1 = 0.f;
        for (int k = 0; k < K; k++) {
            float av = __bfloat162float(A[(size_t)row * lda + k]);
            a0 += av * __bfloat162float(B[(size_t)col * ldb + k]);
            a1 += av * __bfloat162float(B[(size_t)(col + 1) * ldb + k]);
        }
        a0 *= scale; a1 *= scale;
        if (bias)   { a0 += bias[col]; a1 += bias[col + 1]; }
        if (bias2d) { a0 += bias2d[(size_t)row * ld2 + col];
                      a1 += bias2d[(size_t)row * ld2 + col + 1]; }
        if (do_gelu) {
            a0 = 0.5f * a0 * (1.0f + erff(a0 * 0.70710678118654752f));
            a1 = 0.5f * a1 * (1.0f + erff(a1 * 0.70710678118654752f));
        }
        if (residual) { a0 += residual[(size_t)row * ldr + col];
                        a1 += residual[(size_t)row * ldr + col + 1]; }
        if (om == 0) {
            Cf[(size_t)row * ldc + col] = a0;
            Cf[(size_t)row * ldc + col + 1] = a1;
        } else {
            uint32_t w[3];
            if (om == 1) trip_a_w(w, a0, a1); else trip_b_w(w, a0, a1);
            uint32_t* p = (uint32_t*)(C3o + (size_t)row * (3 * (size_t)ldc) + 3 * (size_t)(col + colz));
            p[0] = w[0]; p[1] = w[1]; p[2] = w[2];
        }
    }
#endif
}

// ---------------- combine: out = p0 + p1 + (r) + (bias) -------------------
__global__ void combine_kernel(const float4* __restrict__ p0,
                               const float4* __restrict__ p1,
                               const float4* __restrict__ r,
                               const float4* __restrict__ bias4,
                               float4* __restrict__ out) {
    const int idx = blockIdx.x * 256 + threadIdx.x;   // over U*D/4
    float4 a = p0[idx], b = p1[idx];
    float4 c;
    c.x = a.x + b.x; c.y = a.y + b.y; c.z = a.z + b.z; c.w = a.w + b.w;
    if (r) { float4 rr = r[idx]; c.x += rr.x; c.y += rr.y; c.z += rr.z; c.w += rr.w; }
    if (bias4) {
        float4 bb = bias4[idx & (D / 4 - 1)];
        c.x += bb.x; c.y += bb.y; c.z += bb.z; c.w += bb.w;
    }
    out[idx] = c;
}

// ---------------- triple conversion (fp32 [R,C] -> bf16 [R,3C]) ------------
__global__ void conv_triple_kernel(const float* __restrict__ in,
                                   __nv_bfloat16* __restrict__ out,
                                   size_t n8, int styleB) {
    size_t g = (size_t)blockIdx.x * 256 + threadIdx.x;
    if (g >= n8) return;
    const float4* p = (const float4*)(in + g * 8);
    float4 a = p[0], b = p[1];
    float xs[8] = {a.x, a.y, a.z, a.w, b.x, b.y, b.z, b.w};
    trip8_store((uint4*)(out + g * 24), xs, styleB);
}

// ---------------- RMSNorm -> A-style triple ----------------
__global__ void rmsnorm_triple_kernel(const float* __restrict__ x,
                                      const float* __restrict__ w,
                                      __nv_bfloat16* __restrict__ out) {
    const int row = blockIdx.x;
    const int tid = threadIdx.x;
    __shared__ float red[8];
    const float4* xr = (const float4*)(x + (size_t)row * D + tid * 8);
    const float4* wr = (const float4*)(w + tid * 8);
    float4 xa = xr[0], xb = xr[1];
    float4 wa = wr[0], wb = wr[1];
    float xs[8] = {xa.x, xa.y, xa.z, xa.w, xb.x, xb.y, xb.z, xb.w};
    float ws[8] = {wa.x, wa.y, wa.z, wa.w, wb.x, wb.y, wb.z, wb.w};
    float ss = 0.f;
    #pragma unroll
    for (int i = 0; i < 8; i++) ss += xs[i] * xs[i];
    #pragma unroll
    for (int o = 16; o; o >>= 1) ss += __shfl_xor_sync(0xffffffffu, ss, o);
    if ((tid & 31) == 0) red[tid >> 5] = ss;
    __syncthreads();
    float tot = 0.f;
    #pragma unroll
    for (int i = 0; i < 8; i++) tot += red[i];
    const float r = rsqrtf(tot / (float)D + EPS);
    #pragma unroll
    for (int i = 0; i < 8; i++) xs[i] = xs[i] * r * ws[i];
    trip8_store((uint4*)(out + (size_t)row * K3D + tid * 24), xs, 0);
}

// ---------------- softmax fp32 row -> A-style triple row ----------------
__global__ void softmax_triple_kernel(const float* __restrict__ s,
                                      __nv_bfloat16* __restrict__ out) {
    const size_t row = blockIdx.x;
    const int tid = threadIdx.x;
    __shared__ float red[8];
    const float4* p = (const float4*)(s + row * U + tid * 8);
    float4 a = p[0], b = p[1];
    float xs[8] = {a.x, a.y, a.z, a.w, b.x, b.y, b.z, b.w};

    float m = -1e30f;
    #pragma unroll
    for (int i = 0; i < 8; i++) m = fmaxf(m, xs[i]);
    #pragma unroll
    for (int o = 16; o; o >>= 1) m = fmaxf(m, __shfl_xor_sync(0xffffffffu, m, o));
    if ((tid & 31) == 0) red[tid >> 5] = m;
    __syncthreads();
    #pragma unroll
    for (int i = 0; i < 8; i++) m = fmaxf(m, red[i]);
    __syncthreads();

    float sum = 0.f;
    #pragma unroll
    for (int i = 0; i < 8; i++) { xs[i] = __expf(xs[i] - m); sum += xs[i]; }
    #pragma unroll
    for (int o = 16; o; o >>= 1) sum += __shfl_xor_sync(0xffffffffu, sum, o);
    if ((tid & 31) == 0) red[tid >> 5] = sum;
    __syncthreads();
    float tot = 0.f;
    #pragma unroll
    for (int i = 0; i < 8; i++) tot += red[i];
    const float inv = 1.0f / tot;
    #pragma unroll
    for (int i = 0; i < 8; i++) xs[i] *= inv;
    trip8_store((uint4*)(out + row * (size_t)K3U + tid * 24), xs, 0);
}

// ---------------- v [U,D] -> vT3 [D][3U] B-style transpose ----------------
__global__ void vtrans_kernel(const float* __restrict__ v,
                              __nv_bfloat16* __restrict__ out) {
    const int tx = threadIdx.x & 31, ty = threadIdx.x >> 5;
    const int col = blockIdx.x * 32 + tx;
    const int k0 = blockIdx.y * 64 + ty * 8;
    float xs[8];
    #pragma unroll
    for (int i = 0; i < 8; i++) xs[i] = v[(size_t)(k0 + i) * D + col];
    trip8_store((uint4*)(out + (size_t)col * K3U + (size_t)k0 * 3), xs, 1);
}

// ---------------- launch ----------------
extern "C" void kernel_launch(void* const* d_in, const int* in_sizes, int n_in,
                              void* d_out, int out_size) {
    const float* x   = (const float*)d_in[0];
    const float* adj = (const float*)d_in[1];
    const float* n1w = (const float*)d_in[2];
    const float* n2w = (const float*)d_in[3];
    const float* wq  = (const float*)d_in[4];
    const float* wk  = (const float*)d_in[5];
    const float* wv  = (const float*)d_in[6];
    const float* wo  = (const float*)d_in[7];
    const float* wup = (const float*)d_in[8];
    const float* bup = (const float*)d_in[9];
    const float* wdn = (const float*)d_in[10];
    const float* bdn = (const float*)d_in[11];
    float* out = (float*)d_out;

    static float *sc = nullptr, *x2, *v;
    static __nv_bfloat16 *h3, *q3, *k3, *vT3, *attn3, *ff3,
                         *wqkv3, *wo3, *wup3, *wdn3;
    static bool attr_done = false;
    if (!sc) {
        cudaGetSymbolAddress((void**)&sc, g_scores);
        cudaGetSymbolAddress((void**)&x2, g_x2);
        cudaGetSymbolAddress((void**)&v,  g_v);
        cudaGetSymbolAddress((void**)&h3, g_h3);
        cudaGetSymbolAddress((void**)&q3, g_q3);
        cudaGetSymbolAddress((void**)&k3, g_k3);
        cudaGetSymbolAddress((void**)&vT3, g_vT3);
        cudaGetSymbolAddress((void**)&attn3, g_attn3);
        cudaGetSymbolAddress((void**)&ff3, g_ff3);
        cudaGetSymbolAddress((void**)&wqkv3, g_wqkv3);
        cudaGetSymbolAddress((void**)&wo3, g_wo3);
        cudaGetSymbolAddress((void**)&wup3, g_wup3);
        cudaGetSymbolAddress((void**)&wdn3, g_wdn3);
    }
    if (!attr_done) {
        cudaFuncSetAttribute(tcg_gemm_kernel<256>,
                             cudaFuncAttributeMaxDynamicSharedMemorySize, TCG_SMEM_SZ(256));
        cudaFuncSetAttribute(tcg_gemm_kernel<128>,
                             cudaFuncAttributeMaxDynamicSharedMemorySize, TCG_SMEM_SZ(128));
        attr_done = true;
    }

    const float attn_scale = 0.08838834764831845f; // 1/sqrt(128)
    const size_t WSTRIDE = (size_t)D * K3D;

    // --- weight conversions ---
    {
        size_t n8 = (size_t)D * D / 8;
        int blks = (int)(n8 / 256);
        conv_triple_kernel<<<blks, 256>>>(wq, wqkv3,               n8, 1);
        conv_triple_kernel<<<blks, 256>>>(wk, wqkv3 + WSTRIDE,     n8, 1);
        conv_triple_kernel<<<blks, 256>>>(wv, wqkv3 + 2 * WSTRIDE, n8, 1);
        conv_triple_kernel<<<blks, 256>>>(wo, wo3, n8, 1);
        size_t n8f = (size_t)D_FF * D / 8;
        int blksf = (int)(n8f / 256);
        conv_triple_kernel<<<blksf, 256>>>(wup, wup3, n8f, 1);
        conv_triple_kernel<<<blksf, 256>>>(wdn, wdn3, n8f, 1);
    }

    // 1) h3 = triple(rmsnorm(x, n1w))
    rmsnorm_triple_kernel<<<U, 256>>>(x, n1w, h3);

    // 2) fused QKV: z0->q3 (triple-A), z1->k3 (triple-B), z2->v (fp32)
    dim3 gQKV(D / 256, U / 256, 3);
    tcg_gemm_kernel<256><<<gQKV, 256, TCG_SMEM_SZ(256)>>>(
        h3, K3D, 0, wqkv3, K3D, WSTRIDE,
        v, q3, k3, D, 0, 0, K3D,
        nullptr, nullptr, 0, nullptr, 0, 1.0f, 0, 3);

    // 3) v -> vT3
    vtrans_kernel<<<dim3(D / 32, U / 64), 256>>>(v, vT3);

    // 4) scores[z] = q_z k_z^T * scale + adj
    dim3 gS(U / 256, U / 256, N_HEADS);
    tcg_gemm_kernel<256><<<gS, 256, TCG_SMEM_SZ(256)>>>(
        q3, K3D, (size_t)K3H, k3, K3D, (size_t)K3H,
        sc, nullptr, nullptr, U, (size_t)U * U, 0, K3H,
        nullptr, adj, U, nullptr, 0, attn_scale, 0, 0);

    // 5) softmax -> attn3 (triple-A)
    softmax_triple_kernel<<<N_HEADS * U, 256>>>(sc, attn3);

    // 6) ao3 (reuse h3) = attn3 @ vT3^T, per-head N=128 col slices
    dim3 gPV(1, U / 256, N_HEADS);
    tcg_gemm_kernel<128><<<gPV, 256, TCG_SMEM_SZ(128)>>>(
        attn3, K3U, (size_t)U * K3U, vT3, K3U, (size_t)D_HEAD * K3U,
        nullptr, h3, nullptr, D, 0, D_HEAD, K3U,
        nullptr, nullptr, 0, nullptr, 0, 1.0f, 0, 1);

    // 7) Wo, K-split 2 -> partials in sc
    dim3 gWO(D / 256, U / 256, 2);
    tcg_gemm_kernel<256><<<gWO, 256, TCG_SMEM_SZ(256)>>>(
        h3, K3D, (size_t)(K3D / 2), wo3, K3D, (size_t)(K3D / 2),
        sc, nullptr, nullptr, D, (size_t)U * D, 0, K3D / 2,
        nullptr, nullptr, 0, nullptr, 0, 1.0f, 0, 0);
    // x2 = x + p0 + p1
    combine_kernel<<<(U * D / 4) / 256, 256>>>(
        (const float4*)sc, (const float4*)(sc + (size_t)U * D),
        (const float4*)x, nullptr, (float4*)x2);

    // 8) h3 = triple(rmsnorm(x2, n2w))
    rmsnorm_triple_kernel<<<U, 256>>>(x2, n2w, h3);

    // 9) ff3 = triple-A(gelu(h2 @ wup^T + bup))
    dim3 gUP(D_FF / 256, U / 256, 1);
    tcg_gemm_kernel<256><<<gUP, 256, TCG_SMEM_SZ(256)>>>(
        h3, K3D, 0, wup3, K3D, 0,
        nullptr, ff3, nullptr, D_FF, 0, 0, K3D,
        bup, nullptr, 0, nullptr, 0, 1.0f, 1, 1);

    // 10) down, K-split 2 -> partials in sc
    dim3 gDN(D / 256, U / 256, 2);
    tcg_gemm_kernel<256><<<gDN, 256, TCG_SMEM_SZ(256)>>>(
        ff3, K3F, (size_t)(K3F / 2), wdn3, K3F, (size_t)(K3F / 2),
        sc, nullptr, nullptr, D, (size_t)U * D, 0, K3F / 2,
        nullptr, nullptr, 0, nullptr, 0, 1.0f, 0, 0);
    // out = x2 + p0 + p1 + bdn
    combine_kernel<<<(U * D / 4) / 256, 256>>>(
        (const float4*)sc, (const float4*)(sc + (size_t)U * D),
        (const float4*)x2, (const float4*)bdn, (float4*)out);
}

// round 8
// speedup vs baseline: 5.9964x; 1.2395x over previous
#include <cuda_runtime.h>
#include <cuda_bf16.h>
#include <math.h>
#include <stdint.h>

#define U 2048
#define D 2048
#define N_HEADS 16
#define D_HEAD 128
#define D_FF 8192
#define EPS 1e-6f

#define K3D (3*D)       // 6144
#define K3F (3*D_FF)    // 24576

#if !defined(__CUDA_ARCH__) || defined(__CUDA_ARCH_FEAT_SM103_ALL) || defined(__CUDA_ARCH_FEAT_SM100_ALL) || defined(__CUDA_ARCH_FEAT_SM101_ALL) || defined(__CUDA_ARCH_FEAT_SM110_ALL)
#define HAS_TCG 1
#else
#define HAS_TCG 0
#endif

// ---------------- scratch ----------------
__device__ float g_scores[(size_t)N_HEADS * U * U];   // scores / K-split partials
__device__ float g_x2[(size_t)U * D];
__device__ __nv_bfloat16 g_h1 [(size_t)U * D];
__device__ __nv_bfloat16 g_q1 [(size_t)U * D];
__device__ __nv_bfloat16 g_k1 [(size_t)U * D];
__device__ __nv_bfloat16 g_v1 [(size_t)U * D];
__device__ __nv_bfloat16 g_vT1[(size_t)D * U];
__device__ __nv_bfloat16 g_attn1[(size_t)N_HEADS * U * U];
__device__ __nv_bfloat16 g_ao1[(size_t)U * D];
__device__ __nv_bfloat16 g_h3 [(size_t)U * K3D];
__device__ __nv_bfloat16 g_ff3[(size_t)U * K3F];
__device__ __nv_bfloat16 g_wqkv1[(size_t)3 * D * D];
__device__ __nv_bfloat16 g_wo1[(size_t)D * D];
__device__ __nv_bfloat16 g_wup3[(size_t)D_FF * K3D];
__device__ __nv_bfloat16 g_wdn3[(size_t)D * K3F];

// ---------------- packing helpers ----------------
__device__ __forceinline__ void split2(float x, __nv_bfloat16& hi, __nv_bfloat16& lo) {
    hi = __float2bfloat16(x);
    lo = __float2bfloat16(x - __bfloat162float(hi));
}
__device__ __forceinline__ uint32_t pk(__nv_bfloat16 a, __nv_bfloat16 b) {
    return (uint32_t)__bfloat16_as_ushort(a) | ((uint32_t)__bfloat16_as_ushort(b) << 16);
}
__device__ __forceinline__ void trip_a_w(uint32_t* w, float x0, float x1) {
    __nv_bfloat16 h0, l0, h1, l1; split2(x0, h0, l0); split2(x1, h1, l1);
    w[0] = pk(h0, l0); w[1] = pk(h0, h1); w[2] = pk(l1, h1);
}
__device__ __forceinline__ void trip_b_w(uint32_t* w, float x0, float x1) {
    __nv_bfloat16 h0, l0, h1, l1; split2(x0, h0, l0); split2(x1, h1, l1);
    w[0] = pk(h0, h0); w[1] = pk(l0, h1); w[2] = pk(h1, l1);
}
__device__ __forceinline__ void trip8_store(uint4* dst, const float* xs, int styleB) {
    uint32_t w[12];
    if (styleB) {
        #pragma unroll
        for (int m = 0; m < 4; m++) trip_b_w(w + 3 * m, xs[2 * m], xs[2 * m + 1]);
    } else {
        #pragma unroll
        for (int m = 0; m < 4; m++) trip_a_w(w + 3 * m, xs[2 * m], xs[2 * m + 1]);
    }
    const uint4* v = (const uint4*)w;
    dst[0] = v[0]; dst[1] = v[1]; dst[2] = v[2];
}
// 8 floats -> 8 bf16 -> one uint4
__device__ __forceinline__ void single8_store(uint4* dst, const float* xs) {
    uint32_t w[4];
    #pragma unroll
    for (int m = 0; m < 4; m++)
        w[m] = pk(__float2bfloat16(xs[2 * m]), __float2bfloat16(xs[2 * m + 1]));
    *dst = *(const uint4*)w;
}

__device__ __forceinline__ void cp16(void* smem, const void* gmem) {
    uint32_t s = (uint32_t)__cvta_generic_to_shared(smem);
    asm volatile("cp.async.ca.shared.global [%0], [%1], 16;\n" :: "r"(s), "l"(gmem));
}
__device__ __forceinline__ void cpcommit() { asm volatile("cp.async.commit_group;\n"); }
__device__ __forceinline__ void cpwait0() { asm volatile("cp.async.wait_group 0;\n"); }
__device__ __forceinline__ void cpwait1() { asm volatile("cp.async.wait_group 1;\n"); }

#if HAS_TCG
__device__ __forceinline__ uint32_t elect_one_pred() {
    uint32_t pred;
    asm volatile(
        "{\n\t.reg .pred p;\n\telect.sync _|p, 0xFFFFFFFF;\n\tselp.b32 %0, 1, 0, p;\n\t}"
        : "=r"(pred));
    return pred;
}
#define TCG_ALLOC(dst, n)  asm volatile("tcgen05.alloc.cta_group::1.sync.aligned.shared::cta.b32 [%0], %1;" :: "r"(dst), "r"(n) : "memory")
#define TCG_DEALLOC(t, n)  asm volatile("tcgen05.dealloc.cta_group::1.sync.aligned.b32 %0, %1;" :: "r"(t), "r"(n))
#define TCG_COMMIT(mb)     asm volatile("tcgen05.commit.cta_group::1.mbarrier::arrive::one.shared::cluster.b64 [%0];" :: "r"(mb) : "memory")
#define TCG_FENCE_AFTER()  asm volatile("tcgen05.fence::after_thread_sync;" ::: "memory")
#define TCG_FENCE_BEFORE() asm volatile("tcgen05.fence::before_thread_sync;" ::: "memory")
#define TCG_WAIT_LD()      asm volatile("tcgen05.wait::ld.sync.aligned;" ::: "memory")
#define FENCE_ASYNC_SHARED() asm volatile("fence.proxy.async.shared::cta;" ::: "memory")
#define MBAR_INIT(mb, c)   asm volatile("mbarrier.init.shared.b64 [%0], %1;" :: "r"(mb), "r"(c) : "memory")

__device__ __forceinline__ void mbar_wait_parity(uint32_t mbar, uint32_t parity) {
    uint32_t done;
    asm volatile(
        "{\n\t.reg .pred p;\n\t"
        "mbarrier.try_wait.parity.acquire.cta.shared::cta.b64 p, [%1], %2;\n\t"
        "selp.b32 %0, 1, 0, p;\n\t}"
        : "=r"(done) : "r"(mbar), "r"(parity) : "memory");
    if (!done) {
        asm volatile(
            "{\n\t.reg .pred P1;\n\t"
            "WAIT_LOOP_%=:\n\t"
            "mbarrier.try_wait.parity.acquire.cta.shared::cta.b64 P1, [%0], %1, 0x989680;\n\t"
            "@P1 bra.uni WAIT_DONE_%=;\n\t"
            "bra.uni WAIT_LOOP_%=;\n\t"
            "WAIT_DONE_%=:\n\t}"
            :: "r"(mbar), "r"(parity) : "memory");
    }
}

__device__ __forceinline__ void tcg_ld_x32(uint32_t* r, uint32_t taddr) {
    asm volatile(
        "tcgen05.ld.sync.aligned.32x32b.x32.b32 "
        "{%0,%1,%2,%3,%4,%5,%6,%7,%8,%9,%10,%11,%12,%13,%14,%15,"
        "%16,%17,%18,%19,%20,%21,%22,%23,%24,%25,%26,%27,%28,%29,%30,%31}, [%32];"
        : "=r"(r[0]), "=r"(r[1]), "=r"(r[2]), "=r"(r[3]), "=r"(r[4]), "=r"(r[5]),
          "=r"(r[6]), "=r"(r[7]), "=r"(r[8]), "=r"(r[9]), "=r"(r[10]), "=r"(r[11]),
          "=r"(r[12]), "=r"(r[13]), "=r"(r[14]), "=r"(r[15]), "=r"(r[16]), "=r"(r[17]),
          "=r"(r[18]), "=r"(r[19]), "=r"(r[20]), "=r"(r[21]), "=r"(r[22]), "=r"(r[23]),
          "=r"(r[24]), "=r"(r[25]), "=r"(r[26]), "=r"(r[27]), "=r"(r[28]), "=r"(r[29]),
          "=r"(r[30]), "=r"(r[31])
        : "r"(taddr));
}

__device__ __forceinline__ void tcg_mma_f16_ss(uint32_t d, uint64_t ad, uint64_t bd,
                                               uint32_t idesc, uint32_t en) {
    asm volatile(
        "{\n\t.reg .pred p;\n\tsetp.ne.u32 p, %5, 0;\n\t"
        "tcgen05.mma.cta_group::1.kind::f16 [%0], %1, %2, %3, {%4,%4,%4,%4}, p;\n\t}"
        :: "r"(d), "l"(ad), "l"(bd), "r"(idesc), "r"(0u), "r"(en) : "memory");
}

#define SMEM_DESC_BASE ( (uint64_t(2) << 61) | (uint64_t(1) << 46) \
                       | (uint64_t(64) << 32) | (uint64_t(1) << 16) )
#define MK_DESC(addr) (SMEM_DESC_BASE | ((uint64_t)((addr) >> 4) & 0x3FFF))
#endif

#define SWZ(o) ((o) ^ (((o) >> 3) & 0x70))

// ============== tcgen05 GEMM: M=256 (dual-MMA) x TN, 3-stage pipeline ======
// out_mode: 0 fp32 | 1 triple-A | 2 triple-B | 4 single bf16 |
//           3 QKV (z0->C3, z1->C3b, z2->(bf16*)Cf, all single)
#define ST_A 32768
#define TCG_SMEM_SZ(TN) (1024 + 3 * ST_A + 3 * ((TN) * 128))

extern __shared__ char tcg_smem[];

template<int TN>
__global__ __launch_bounds__(256)
void tcg_gemm_kernel(const __nv_bfloat16* __restrict__ A, int lda, size_t sA,
                     const __nv_bfloat16* __restrict__ B, int ldb, size_t sB,
                     float* __restrict__ Cf, __nv_bfloat16* __restrict__ C3,
                     __nv_bfloat16* __restrict__ C3b,
                     int ldc, size_t sC, int czcol,
                     int K,
                     const float* __restrict__ bias,
                     const float* __restrict__ bias2d, int ld2,
                     const float* __restrict__ residual, int ldr,
                     float scale, int do_gelu, int out_mode) {
    constexpr uint32_t IDESC = (1u << 4) | (1u << 7) | (1u << 10)
                             | ((TN / 8) << 17) | (8u << 24);
    constexpr int ST_B = TN * 128;
    const int z = blockIdx.z;
    A += (size_t)z * sA;
    B += (size_t)z * sB;
    if (Cf) Cf += (size_t)z * sC;
    const int colz = z * czcol;

    const int tid = threadIdx.x;
    const int wid = tid >> 5, lane = tid & 31;
    const int bm = blockIdx.y * 256;
    const int bn = blockIdx.x * TN;

    int om = out_mode;
    __nv_bfloat16* C3o = C3;
    if (out_mode == 3) {
        om = 4;
        C3o = (z == 0) ? C3 : (z == 1) ? C3b : (__nv_bfloat16*)Cf;
    }

#if HAS_TCG
    const uint32_t smem_base = (uint32_t)__cvta_generic_to_shared(tcg_smem);

    if (wid == 0) TCG_ALLOC(smem_base, 512);
    if (tid == 0) {
        MBAR_INIT(smem_base + 8,  1);
        MBAR_INIT(smem_base + 16, 1);
        MBAR_INIT(smem_base + 24, 1);
    }
    __syncthreads();
    uint32_t tmem_base;
    asm volatile("ld.shared.b32 %0, [%1];" : "=r"(tmem_base) : "r"(smem_base));

    auto load_stage = [&](int s, int k0) {
        char* sa = tcg_smem + 1024 + s * ST_A;
        char* sb = tcg_smem + 1024 + 3 * ST_A + s * ST_B;
        #pragma unroll
        for (int i = 0; i < 8; i++) {
            int c = i * 256 + tid;
            int row = c >> 3, sub = c & 7;
            cp16(sa + SWZ(row * 128 + sub * 16),
                 A + (size_t)(bm + row) * lda + k0 + sub * 8);
        }
        #pragma unroll
        for (int i = 0; i < TN / 32; i++) {
            int c = i * 256 + tid;
            int row = c >> 3, sub = c & 7;
            cp16(sb + SWZ(row * 128 + sub * 16),
                 B + (size_t)(bn + row) * ldb + k0 + sub * 8);
        }
    };

    const int nIter = K / 64;

    load_stage(0, 0);  cpcommit();
    load_stage(1, 64); cpcommit();

    for (int it = 0; it < nIter; it++) {
        const int s = it % 3;
        if (it + 1 < nIter) cpwait1(); else cpwait0();
        __syncthreads();

        if (wid == 0) {
            if (elect_one_pred()) {
                FENCE_ASYNC_SHARED();
                uint64_t ad = MK_DESC(smem_base + 1024 + s * ST_A);
                uint64_t bd = MK_DESC(smem_base + 1024 + 3 * ST_A + s * ST_B);
                #pragma unroll
                for (int ks = 0; ks < 4; ks++) {
                    uint32_t en = (it > 0 || ks > 0) ? 1u : 0u;
                    tcg_mma_f16_ss(tmem_base,       ad + ks * 2,        bd + ks * 2, IDESC, en);
                    tcg_mma_f16_ss(tmem_base + 256, ad + 1024 + ks * 2, bd + ks * 2, IDESC, en);
                }
                TCG_COMMIT(smem_base + 8 + s * 8);
            }
        }

        if (it + 2 < nIter) {
            const int sl = (it + 2) % 3;
            if (it + 2 >= 3) {
                const int n = (it + 2) / 3;
                mbar_wait_parity(smem_base + 8 + sl * 8, (uint32_t)((n - 1) & 1));
            }
            load_stage(sl, (it + 2) * 64);
            cpcommit();
        }
    }

    {
        const int sl = (nIter - 1) % 3;
        const int n = (nIter - 1) / 3 + 1;
        mbar_wait_parity(smem_base + 8 + sl * 8, (uint32_t)((n - 1) & 1));
    }
    TCG_FENCE_AFTER();

    const int h = wid >> 2;
    const int row = bm + h * 128 + (wid & 3) * 32 + lane;
    #pragma unroll
    for (int ch = 0; ch < TN / 32; ch++) {
        const int c0 = ch * 32;
        uint32_t r[32];
        tcg_ld_x32(r, tmem_base + h * 256 + c0);
        TCG_WAIT_LD();
        float vals[32];
        #pragma unroll
        for (int j = 0; j < 32; j++) {
            const int col = bn + c0 + j;
            float v = __uint_as_float(r[j]) * scale;
            if (bias)   v += bias[col];
            if (bias2d) v += bias2d[(size_t)row * ld2 + col];
            if (do_gelu) v = 0.5f * v * (1.0f + erff(v * 0.70710678118654752f));
            if (residual) v += residual[(size_t)row * ldr + col];
            vals[j] = v;
        }
        if (om == 0) {
            float4* dst = (float4*)(Cf + (size_t)row * ldc + bn + c0);
            const float4* src = (const float4*)vals;
            #pragma unroll
            for (int q = 0; q < 8; q++) dst[q] = src[q];
        } else if (om == 4) {
            uint32_t w[16];
            #pragma unroll
            for (int p = 0; p < 16; p++)
                w[p] = pk(__float2bfloat16(vals[2 * p]), __float2bfloat16(vals[2 * p + 1]));
            uint4* dst = (uint4*)(C3o + (size_t)row * ldc + (bn + c0 + colz));
            const uint4* src = (const uint4*)w;
            #pragma unroll
            for (int q = 0; q < 4; q++) dst[q] = src[q];
        } else {
            uint32_t w[48];
            #pragma unroll
            for (int p = 0; p < 16; p++) {
                if (om == 1) trip_a_w(w + 3 * p, vals[2 * p], vals[2 * p + 1]);
                else         trip_b_w(w + 3 * p, vals[2 * p], vals[2 * p + 1]);
            }
            uint4* dst = (uint4*)(C3o + (size_t)row * (3 * (size_t)ldc)
                                  + 3 * (size_t)(bn + c0 + colz));
            const uint4* src = (const uint4*)w;
            #pragma unroll
            for (int q = 0; q < 12; q++) dst[q] = src[q];
        }
    }

    TCG_FENCE_BEFORE();
    __syncthreads();
    if (wid == 0) TCG_DEALLOC(tmem_base, 512);

#else
    // compile-only fallback for non-'a' PTX stage
    for (int idx = tid; idx < 256 * (TN / 2); idx += 256) {
        const int mi = idx / (TN / 2);
        const int p2 = idx % (TN / 2);
        const int row = bm + mi;
        const int col = bn + 2 * p2;
        float a0 = 0.f, a1 = 0.f;
        for (int k = 0; k < K; k++) {
            float av = __bfloat162float(A[(size_t)row * lda + k]);
            a0 += av * __bfloat162float(B[(size_t)col * ldb + k]);
            a1 += av * __bfloat162float(B[(size_t)(col + 1) * ldb + k]);
        }
        a0 *= scale; a1 *= scale;
        if (bias)   { a0 += bias[col]; a1 += bias[col + 1]; }
        if (bias2d) { a0 += bias2d[(size_t)row * ld2 + col];
                      a1 += bias2d[(size_t)row * ld2 + col + 1]; }
        if (do_gelu) {
            a0 = 0.5f * a0 * (1.0f + erff(a0 * 0.70710678118654752f));
            a1 = 0.5f * a1 * (1.0f + erff(a1 * 0.70710678118654752f));
        }
        if (residual) { a0 += residual[(size_t)row * ldr + col];
                        a1 += residual[(size_t)row * ldr + col + 1]; }
        if (om == 0) {
            Cf[(size_t)row * ldc + col] = a0;
            Cf[(size_t)row * ldc + col + 1] = a1;
        } else if (om == 4) {
            C3o[(size_t)row * ldc + col + colz] = __float2bfloat16(a0);
            C3o[(size_t)row * ldc + col + colz + 1] = __float2bfloat16(a1);
        } else {
            uint32_t w[3];
            if (om == 1) trip_a_w(w, a0, a1); else trip_b_w(w, a0, a1);
            uint32_t* p = (uint32_t*)(C3o + (size_t)row * (3 * (size_t)ldc) + 3 * (size_t)(col + colz));
            p[0] = w[0]; p[1] = w[1]; p[2] = w[2];
        }
    }
#endif
}

// ---------------- combine: out = p0 + p1 + (r) + (bias) -------------------
__global__ void combine_kernel(const float4* __restrict__ p0,
                               const float4* __restrict__ p1,
                               const float4* __restrict__ r,
                               const float4* __restrict__ bias4,
                               float4* __restrict__ out) {
    const int idx = blockIdx.x * 256 + threadIdx.x;
    float4 a = p0[idx], b = p1[idx];
    float4 c;
    c.x = a.x + b.x; c.y = a.y + b.y; c.z = a.z + b.z; c.w = a.w + b.w;
    if (r) { float4 rr = r[idx]; c.x += rr.x; c.y += rr.y; c.z += rr.z; c.w += rr.w; }
    if (bias4) {
        float4 bb = bias4[idx & (D / 4 - 1)];
        c.x += bb.x; c.y += bb.y; c.z += bb.z; c.w += bb.w;
    }
    out[idx] = c;
}

// ---------------- conversions ----------------
__global__ void conv_triple_kernel(const float* __restrict__ in,
                                   __nv_bfloat16* __restrict__ out,
                                   size_t n8, int styleB) {
    size_t g = (size_t)blockIdx.x * 256 + threadIdx.x;
    if (g >= n8) return;
    const float4* p = (const float4*)(in + g * 8);
    float4 a = p[0], b = p[1];
    float xs[8] = {a.x, a.y, a.z, a.w, b.x, b.y, b.z, b.w};
    trip8_store((uint4*)(out + g * 24), xs, styleB);
}

__global__ void conv_single_kernel(const float* __restrict__ in,
                                   __nv_bfloat16* __restrict__ out,
                                   size_t n8) {
    size_t g = (size_t)blockIdx.x * 256 + threadIdx.x;
    if (g >= n8) return;
    const float4* p = (const float4*)(in + g * 8);
    float4 a = p[0], b = p[1];
    float xs[8] = {a.x, a.y, a.z, a.w, b.x, b.y, b.z, b.w};
    single8_store((uint4*)(out + g * 8), xs);
}

// ---------------- RMSNorm (mode 0 = single, 1 = triple-A) ------------------
template<int TRIPLE>
__global__ void rmsnorm_kernel(const float* __restrict__ x,
                               const float* __restrict__ w,
                               __nv_bfloat16* __restrict__ out) {
    const int row = blockIdx.x;
    const int tid = threadIdx.x;
    __shared__ float red[8];
    const float4* xr = (const float4*)(x + (size_t)row * D + tid * 8);
    const float4* wr = (const float4*)(w + tid * 8);
    float4 xa = xr[0], xb = xr[1];
    float4 wa = wr[0], wb = wr[1];
    float xs[8] = {xa.x, xa.y, xa.z, xa.w, xb.x, xb.y, xb.z, xb.w};
    float ws[8] = {wa.x, wa.y, wa.z, wa.w, wb.x, wb.y, wb.z, wb.w};
    float ss = 0.f;
    #pragma unroll
    for (int i = 0; i < 8; i++) ss += xs[i] * xs[i];
    #pragma unroll
    for (int o = 16; o; o >>= 1) ss += __shfl_xor_sync(0xffffffffu, ss, o);
    if ((tid & 31) == 0) red[tid >> 5] = ss;
    __syncthreads();
    float tot = 0.f;
    #pragma unroll
    for (int i = 0; i < 8; i++) tot += red[i];
    const float r = rsqrtf(tot / (float)D + EPS);
    #pragma unroll
    for (int i = 0; i < 8; i++) xs[i] = xs[i] * r * ws[i];
    if (TRIPLE)
        trip8_store((uint4*)(out + (size_t)row * K3D + tid * 24), xs, 0);
    else
        single8_store((uint4*)(out + (size_t)row * D + tid * 8), xs);
}

// ---------------- softmax fp32 row -> single bf16 row ----------------------
__global__ void softmax_single_kernel(const float* __restrict__ s,
                                      __nv_bfloat16* __restrict__ out) {
    const size_t row = blockIdx.x;
    const int tid = threadIdx.x;
    __shared__ float red[8];
    const float4* p = (const float4*)(s + row * U + tid * 8);
    float4 a = p[0], b = p[1];
    float xs[8] = {a.x, a.y, a.z, a.w, b.x, b.y, b.z, b.w};

    float m = -1e30f;
    #pragma unroll
    for (int i = 0; i < 8; i++) m = fmaxf(m, xs[i]);
    #pragma unroll
    for (int o = 16; o; o >>= 1) m = fmaxf(m, __shfl_xor_sync(0xffffffffu, m, o));
    if ((tid & 31) == 0) red[tid >> 5] = m;
    __syncthreads();
    #pragma unroll
    for (int i = 0; i < 8; i++) m = fmaxf(m, red[i]);
    __syncthreads();

    float sum = 0.f;
    #pragma unroll
    for (int i = 0; i < 8; i++) { xs[i] = __expf(xs[i] - m); sum += xs[i]; }
    #pragma unroll
    for (int o = 16; o; o >>= 1) sum += __shfl_xor_sync(0xffffffffu, sum, o);
    if ((tid & 31) == 0) red[tid >> 5] = sum;
    __syncthreads();
    float tot = 0.f;
    #pragma unroll
    for (int i = 0; i < 8; i++) tot += red[i];
    const float inv = 1.0f / tot;
    #pragma unroll
    for (int i = 0; i < 8; i++) xs[i] *= inv;
    single8_store((uint4*)(out + row * (size_t)U + tid * 8), xs);
}

// ---------------- v1 [U,D] bf16 -> vT1 [D,U] bf16 transpose ----------------
__global__ void vtrans_kernel(const __nv_bfloat16* __restrict__ v,
                              __nv_bfloat16* __restrict__ out) {
    const int tx = threadIdx.x & 31, ty = threadIdx.x >> 5;
    const int col = blockIdx.x * 32 + tx;
    const int k0 = blockIdx.y * 64 + ty * 8;
    uint32_t w[4];
    #pragma unroll
    for (int m = 0; m < 4; m++)
        w[m] = pk(v[(size_t)(k0 + 2 * m) * D + col], v[(size_t)(k0 + 2 * m + 1) * D + col]);
    *(uint4*)(out + (size_t)col * U + k0) = *(const uint4*)w;
}

// ---------------- launch ----------------
extern "C" void kernel_launch(void* const* d_in, const int* in_sizes, int n_in,
                              void* d_out, int out_size) {
    const float* x   = (const float*)d_in[0];
    const float* adj = (const float*)d_in[1];
    const float* n1w = (const float*)d_in[2];
    const float* n2w = (const float*)d_in[3];
    const float* wq  = (const float*)d_in[4];
    const float* wk  = (const float*)d_in[5];
    const float* wv  = (const float*)d_in[6];
    const float* wo  = (const float*)d_in[7];
    const float* wup = (const float*)d_in[8];
    const float* bup = (const float*)d_in[9];
    const float* wdn = (const float*)d_in[10];
    const float* bdn = (const float*)d_in[11];
    float* out = (float*)d_out;

    static float *sc = nullptr, *x2;
    static __nv_bfloat16 *h1, *q1, *k1, *v1, *vT1, *attn1, *ao1, *h3, *ff3,
                         *wqkv1, *wo1, *wup3, *wdn3;
    static bool attr_done = false;
    if (!sc) {
        cudaGetSymbolAddress((void**)&sc, g_scores);
        cudaGetSymbolAddress((void**)&x2, g_x2);
        cudaGetSymbolAddress((void**)&h1, g_h1);
        cudaGetSymbolAddress((void**)&q1, g_q1);
        cudaGetSymbolAddress((void**)&k1, g_k1);
        cudaGetSymbolAddress((void**)&v1, g_v1);
        cudaGetSymbolAddress((void**)&vT1, g_vT1);
        cudaGetSymbolAddress((void**)&attn1, g_attn1);
        cudaGetSymbolAddress((void**)&ao1, g_ao1);
        cudaGetSymbolAddress((void**)&h3, g_h3);
        cudaGetSymbolAddress((void**)&ff3, g_ff3);
        cudaGetSymbolAddress((void**)&wqkv1, g_wqkv1);
        cudaGetSymbolAddress((void**)&wo1, g_wo1);
        cudaGetSymbolAddress((void**)&wup3, g_wup3);
        cudaGetSymbolAddress((void**)&wdn3, g_wdn3);
    }
    if (!attr_done) {
        cudaFuncSetAttribute(tcg_gemm_kernel<256>,
                             cudaFuncAttributeMaxDynamicSharedMemorySize, TCG_SMEM_SZ(256));
        cudaFuncSetAttribute(tcg_gemm_kernel<128>,
                             cudaFuncAttributeMaxDynamicSharedMemorySize, TCG_SMEM_SZ(128));
        attr_done = true;
    }

    const float attn_scale = 0.08838834764831845f; // 1/sqrt(128)

    // --- weight conversions ---
    {
        size_t n8 = (size_t)D * D / 8;
        int blks = (int)(n8 / 256);
        conv_single_kernel<<<blks, 256>>>(wq, wqkv1,                    n8);
        conv_single_kernel<<<blks, 256>>>(wk, wqkv1 + (size_t)D * D,    n8);
        conv_single_kernel<<<blks, 256>>>(wv, wqkv1 + 2 * (size_t)D * D, n8);
        conv_single_kernel<<<blks, 256>>>(wo, wo1, n8);
        size_t n8f = (size_t)D_FF * D / 8;
        int blksf = (int)(n8f / 256);
        conv_triple_kernel<<<blksf, 256>>>(wup, wup3, n8f, 1);
        conv_triple_kernel<<<blksf, 256>>>(wdn, wdn3, n8f, 1);
    }

    // 1) h1 = single(rmsnorm(x, n1w))
    rmsnorm_kernel<0><<<U, 256>>>(x, n1w, h1);

    // 2) fused QKV (single, K=2048): z0->q1, z1->k1, z2->v1
    dim3 gQKV(D / 256, U / 256, 3);
    tcg_gemm_kernel<256><<<gQKV, 256, TCG_SMEM_SZ(256)>>>(
        h1, D, 0, wqkv1, D, (size_t)D * D,
        (float*)v1, q1, k1, D, 0, 0, D,
        nullptr, nullptr, 0, nullptr, 0, 1.0f, 0, 3);

    // 3) v1 -> vT1
    vtrans_kernel<<<dim3(D / 32, U / 64), 256>>>(v1, vT1);

    // 4) scores[z] = q_z k_z^T * scale + adj  (K=128 per head)
    dim3 gS(U / 256, U / 256, N_HEADS);
    tcg_gemm_kernel<256><<<gS, 256, TCG_SMEM_SZ(256)>>>(
        q1, D, (size_t)D_HEAD, k1, D, (size_t)D_HEAD,
        sc, nullptr, nullptr, U, (size_t)U * U, 0, D_HEAD,
        nullptr, adj, U, nullptr, 0, attn_scale, 0, 0);

    // 5) softmax -> attn1 (single bf16)
    softmax_single_kernel<<<N_HEADS * U, 256>>>(sc, attn1);

    // 6) ao1 = attn1 @ vT1^T (K=2048), per-head N=128 col slices
    dim3 gPV(1, U / 256, N_HEADS);
    tcg_gemm_kernel<128><<<gPV, 256, TCG_SMEM_SZ(128)>>>(
        attn1, U, (size_t)U * U, vT1, U, (size_t)D_HEAD * U,
        nullptr, ao1, nullptr, D, 0, D_HEAD, U,
        nullptr, nullptr, 0, nullptr, 0, 1.0f, 0, 4);

    // 7) Wo (single, K=2048), K-split 2 -> partials in sc
    dim3 gWO(D / 256, U / 256, 2);
    tcg_gemm_kernel<256><<<gWO, 256, TCG_SMEM_SZ(256)>>>(
        ao1, D, (size_t)(D / 2), wo1, D, (size_t)(D / 2),
        sc, nullptr, nullptr, D, (size_t)U * D, 0, D / 2,
        nullptr, nullptr, 0, nullptr, 0, 1.0f, 0, 0);
    combine_kernel<<<(U * D / 4) / 256, 256>>>(
        (const float4*)sc, (const float4*)(sc + (size_t)U * D),
        (const float4*)x, nullptr, (float4*)x2);

    // 8) h3 = triple(rmsnorm(x2, n2w))
    rmsnorm_kernel<1><<<U, 256>>>(x2, n2w, h3);

    // 9) ff3 = triple-A(gelu(h2 @ wup^T + bup))  (triple, K=6144)
    dim3 gUP(D_FF / 256, U / 256, 1);
    tcg_gemm_kernel<256><<<gUP, 256, TCG_SMEM_SZ(256)>>>(
        h3, K3D, 0, wup3, K3D, 0,
        nullptr, ff3, nullptr, D_FF, 0, 0, K3D,
        bup, nullptr, 0, nullptr, 0, 1.0f, 1, 1);

    // 10) down (triple, K=24576), K-split 2 -> partials in sc
    dim3 gDN(D / 256, U / 256, 2);
    tcg_gemm_kernel<256><<<gDN, 256, TCG_SMEM_SZ(256)>>>(
        ff3, K3F, (size_t)(K3F / 2), wdn3, K3F, (size_t)(K3F / 2),
        sc, nullptr, nullptr, D, (size_t)U * D, 0, K3F / 2,
        nullptr, nullptr, 0, nullptr, 0, 1.0f, 0, 0);
    combine_kernel<<<(U * D / 4) / 256, 256>>>(
        (const float4*)sc, (const float4*)(sc + (size_t)U * D),
        (const float4*)x2, (const float4*)bdn, (float4*)out);
}